// round 15
// baseline (speedup 1.0000x reference)
#include <cuda_runtime.h>
#include <cuda_fp16.h>
#include <math.h>
#include <stdint.h>

#define NB 4
#define NN 4096
#define NSQ ((size_t)NN * (size_t)NN)

// ---------------- scratch (device globals: allocation-free) ----------------
__device__ float g_A[(size_t)NB * NSQ];       // 268 MB: S (gram, symmetric)
__device__ float g_t[(size_t)NB * 128 * NN];  // split-K partial 0 / layer buffers
__device__ float g_y[(size_t)NB * 128 * NN];  // split-K partial 1 / layer buffers
__device__ float g_x[(size_t)NB * 128 * NN];  // split-K partial 2
__device__ float g_z[(size_t)NB * 128 * NN];  // split-K partial 3
__device__ float g_w[(size_t)NB * 128 * NN];  // conv outputs
__device__ float g_sums[128];
__device__ float g_sumsq[128];
__device__ float g_scale[128];
__device__ float g_shift[128];
__device__ float g_M[NB * 32 * 32];
__device__ float g_mx[NB * NN];                    // per-row adj = max + ln(sumexp)
__device__ float g_pmx[(size_t)NB * NN * 32];      // per-(row, m-tile) partial max
__device__ float g_pse[(size_t)NB * NN * 32];      // per-(row, m-tile) partial sumexp
__device__ __half g_xs[2][(size_t)NB * 128 * NN];  // x / X natural, 2 fp16 planes
__device__ __half g_xT[2][(size_t)NB * NN * 128];  // x transposed, 2 fp16 planes

__device__ __forceinline__ uint32_t smem_u32(const void* p) {
    uint32_t a;
    asm("{ .reg .u64 t; cvta.to.shared.u64 t, %1; cvt.u32.u64 %0, t; }" : "=r"(a) : "l"(p));
    return a;
}

#define LDSM4(r0, r1, r2, r3, addr) \
    asm volatile("ldmatrix.sync.aligned.m8n8.x4.shared.b16 {%0,%1,%2,%3}, [%4];" \
        : "=r"(r0), "=r"(r1), "=r"(r2), "=r"(r3) : "r"(addr))

#define MMAH(d, a, b0, b1) \
    asm volatile("mma.sync.aligned.m16n8k16.row.col.f32.f16.f16.f32 " \
        "{%0,%1,%2,%3},{%4,%5,%6,%7},{%8,%9},{%0,%1,%2,%3};" \
        : "+f"((d)[0]), "+f"((d)[1]), "+f"((d)[2]), "+f"((d)[3]) \
        : "r"((a)[0]), "r"((a)[1]), "r"((a)[2]), "r"((a)[3]), "r"(b0), "r"(b1))

#define CPASYNC16(dst, src) \
    asm volatile("cp.async.cg.shared.global [%0], [%1], 16;" :: "r"(dst), "l"(src))
#define CPCOMMIT() asm volatile("cp.async.commit_group;" ::: "memory")
#define CPWAIT(n)  asm volatile("cp.async.wait_group %0;" :: "n"(n) : "memory")

__device__ __forceinline__ void split2h(float v, __half& h0, __half& h1) {
    h0 = __float2half(v);
    h1 = __float2half(v - __half2float(h0));
}

// Fragment-reuse MMA block for one ks-step: terms (a0,b0), (a0,b1), (a1,b0).
// 12 LDSM4 / 48 MMAs per call.
__device__ __forceinline__ void mma_3term_ks(uint32_t aoff, uint32_t boff,
                                             float acc[4][4][4]) {
    uint32_t aq[4][4], bq0[2][4], bq1[2][4];
#pragma unroll
    for (int am = 0; am < 4; am++)
        LDSM4(aq[am][0], aq[am][1], aq[am][2], aq[am][3], aoff + am * 1280);
#pragma unroll
    for (int np = 0; np < 2; np++)
        LDSM4(bq0[np][0], bq0[np][1], bq0[np][2], bq0[np][3], boff + np * 1280);
#pragma unroll
    for (int am = 0; am < 4; am++)
#pragma unroll
        for (int an = 0; an < 4; an++)
            MMAH(acc[am][an], aq[am], bq0[an >> 1][(an & 1) * 2], bq0[an >> 1][(an & 1) * 2 + 1]);
#pragma unroll
    for (int np = 0; np < 2; np++)
        LDSM4(bq1[np][0], bq1[np][1], bq1[np][2], bq1[np][3], boff + 10240 + np * 1280);
#pragma unroll
    for (int am = 0; am < 4; am++)
#pragma unroll
        for (int an = 0; an < 4; an++)
            MMAH(acc[am][an], aq[am], bq1[an >> 1][(an & 1) * 2], bq1[an >> 1][(an & 1) * 2 + 1]);
#pragma unroll
    for (int am = 0; am < 4; am++)
        LDSM4(aq[am][0], aq[am][1], aq[am][2], aq[am][3], aoff + 10240 + am * 1280);
#pragma unroll
    for (int am = 0; am < 4; am++)
#pragma unroll
        for (int an = 0; an < 4; an++)
            MMAH(acc[am][an], aq[am], bq0[an >> 1][(an & 1) * 2], bq0[an >> 1][(an & 1) * 2 + 1]);
}

// ---------------- mma.sync fp16 split GEMM (gram): D = Aop * Bop^T -----------
template <int SYM>
__global__ __launch_bounds__(256, 2) void mma_gemm(
    const __half* __restrict__ Ab, size_t planeA, size_t pitchA, size_t batchA,
    const __half* __restrict__ Bb, size_t planeB, size_t pitchB, size_t batchB,
    float* __restrict__ C, size_t ldC, size_t batchC, int K) {
    extern __shared__ char sm[];
    constexpr int STAGE = 40960;  // 4 planes x 10240
    const int bxm = blockIdx.x, byn = blockIdx.y, b = blockIdx.z;
    if (SYM && bxm < byn) return;
    const int tid = threadIdx.x, lane = tid & 31, wid = tid >> 5;
    const int wm = wid & 1, wn = wid >> 1;
    const __half* Abase = Ab + (size_t)b * batchA + (size_t)(byn * 128) * pitchA;
    const __half* Bbase = Bb + (size_t)b * batchB + (size_t)(bxm * 128) * pitchB;

    float acc[4][4][4];
#pragma unroll
    for (int i = 0; i < 4; i++)
#pragma unroll
        for (int j = 0; j < 4; j++)
#pragma unroll
            for (int r = 0; r < 4; r++) acc[i][j][r] = 0.f;

    const uint32_t smb = smem_u32(sm);
    const uint32_t aoff_rel = (uint32_t)((wm * 64 + (lane & 15)) * 80 + ((lane >> 4) & 1) * 16);
    const uint32_t boff_rel = 20480u +
                              (uint32_t)((wn * 32 + (lane & 7) + ((lane >> 4) & 1) * 8) * 80 +
                                         ((lane >> 3) & 1) * 16);

    const int KT = K >> 5;
    auto issue = [&](int kt, int buf) {
        const int k0 = kt << 5;
        const uint32_t sbase = smb + buf * STAGE;
#pragma unroll
        for (int i = tid; i < 2048; i += 256) {
            int pl = i >> 9, rem = i & 511, row = rem >> 2, u = rem & 3;
            const __half* src = (pl < 2)
                ? Abase + (size_t)pl * planeA + (size_t)row * pitchA + k0 + u * 8
                : Bbase + (size_t)(pl - 2) * planeB + (size_t)row * pitchB + k0 + u * 8;
            CPASYNC16(sbase + pl * 10240 + row * 80 + u * 16, src);
        }
        CPCOMMIT();
    };

    issue(0, 0);
    int buf = 0;
    for (int kt = 0; kt < KT; kt++) {
        if (kt + 1 < KT) {
            issue(kt + 1, buf ^ 1);
            CPWAIT(1);
        } else {
            CPWAIT(0);
        }
        __syncthreads();
        const uint32_t sb = smb + buf * STAGE;
#pragma unroll
        for (int ks = 0; ks < 2; ks++)
            mma_3term_ks(sb + aoff_rel + ks * 32, sb + boff_rel + ks * 32, acc);
        __syncthreads();
        buf ^= 1;
    }
    const int g = lane >> 2, tq = lane & 3;
    float* Cb = C + (size_t)b * batchC + (size_t)(bxm * 128 + wn * 32);
#pragma unroll
    for (int am = 0; am < 4; am++) {
        size_t r0 = (size_t)(byn * 128 + wm * 64 + am * 16 + g);
#pragma unroll
        for (int an = 0; an < 4; an++) {
            int c = an * 8 + tq * 2;
            *reinterpret_cast<float2*>(&Cb[r0 * ldC + c]) =
                make_float2(acc[am][an][0], acc[am][an][1]);
            *reinterpret_cast<float2*>(&Cb[(r0 + 8) * ldC + c]) =
                make_float2(acc[am][an][2], acc[am][an][3]);
        }
    }
    float* sPM1 = reinterpret_cast<float*>(sm);
    float* sPS1 = reinterpret_cast<float*>(sm + 2048);
    float* sPM2 = reinterpret_cast<float*>(sm + 4096);
    float* sPS2 = reinterpret_cast<float*>(sm + 5120);
    float* st = reinterpret_cast<float*>(sm + 8192);

#pragma unroll
    for (int am = 0; am < 4; am++) {
#pragma unroll
        for (int half = 0; half < 2; half++) {
            float m = -3.4e38f;
#pragma unroll
            for (int an = 0; an < 4; an++)
                m = fmaxf(m, fmaxf(acc[am][an][half * 2], acc[am][an][half * 2 + 1]));
            m = fmaxf(m, __shfl_xor_sync(~0u, m, 1));
            m = fmaxf(m, __shfl_xor_sync(~0u, m, 2));
            float se = 0.f;
#pragma unroll
            for (int an = 0; an < 4; an++)
                se += __expf(acc[am][an][half * 2] - m) + __expf(acc[am][an][half * 2 + 1] - m);
            se += __shfl_xor_sync(~0u, se, 1);
            se += __shfl_xor_sync(~0u, se, 2);
            if (tq == 0) {
                int row = wm * 64 + am * 16 + half * 8 + g;
                sPM1[wn * 128 + row] = m;
                sPS1[wn * 128 + row] = se;
            }
        }
    }
    if (SYM && bxm != byn) {
#pragma unroll
        for (int an = 0; an < 4; an++) {
#pragma unroll
            for (int sub = 0; sub < 2; sub++) {
                float m = -3.4e38f;
#pragma unroll
                for (int am = 0; am < 4; am++)
                    m = fmaxf(m, fmaxf(acc[am][an][sub], acc[am][an][2 + sub]));
                m = fmaxf(m, __shfl_xor_sync(~0u, m, 4));
                m = fmaxf(m, __shfl_xor_sync(~0u, m, 8));
                m = fmaxf(m, __shfl_xor_sync(~0u, m, 16));
                float se = 0.f;
#pragma unroll
                for (int am = 0; am < 4; am++)
                    se += __expf(acc[am][an][sub] - m) + __expf(acc[am][an][2 + sub] - m);
                se += __shfl_xor_sync(~0u, se, 4);
                se += __shfl_xor_sync(~0u, se, 8);
                se += __shfl_xor_sync(~0u, se, 16);
                if (g == 0) {
                    int col = wn * 32 + an * 8 + tq * 2 + sub;
                    sPM2[wm * 128 + col] = m;
                    sPS2[wm * 128 + col] = se;
                }
            }
        }
#pragma unroll
        for (int am = 0; am < 4; am++) {
            int rl = wm * 64 + am * 16 + g;
#pragma unroll
            for (int an = 0; an < 4; an++) {
                int cl = wn * 32 + an * 8 + tq * 2;
                st[(size_t)cl * 132 + rl] = acc[am][an][0];
                st[(size_t)(cl + 1) * 132 + rl] = acc[am][an][1];
                st[(size_t)cl * 132 + rl + 8] = acc[am][an][2];
                st[(size_t)(cl + 1) * 132 + rl + 8] = acc[am][an][3];
            }
        }
    }
    __syncthreads();
    if (tid < 128) {
        float m0 = sPM1[tid], m1 = sPM1[128 + tid], m2 = sPM1[256 + tid], m3 = sPM1[384 + tid];
        float m = fmaxf(fmaxf(m0, m1), fmaxf(m2, m3));
        float se = sPS1[tid] * __expf(m0 - m) + sPS1[128 + tid] * __expf(m1 - m) +
                   sPS1[256 + tid] * __expf(m2 - m) + sPS1[384 + tid] * __expf(m3 - m);
        size_t idx = (((size_t)b * NN) + byn * 128 + tid) * 32 + bxm;
        g_pmx[idx] = m;
        g_pse[idx] = se;
    } else if (SYM && bxm != byn) {
        int r = tid - 128;
        float m0 = sPM2[r], m1 = sPM2[128 + r];
        float m = fmaxf(m0, m1);
        float se = sPS2[r] * __expf(m0 - m) + sPS2[128 + r] * __expf(m1 - m);
        size_t idx = (((size_t)b * NN) + bxm * 128 + r) * 32 + byn;
        g_pmx[idx] = m;
        g_pse[idx] = se;
    }
    if (SYM && bxm != byn) {
        float* Cm = C + (size_t)b * batchC;
        for (int i = tid; i < 4096; i += 256) {
            int rp = i >> 5, c4 = (i & 31) * 4;
            float4 v = *reinterpret_cast<const float4*>(&st[(size_t)rp * 132 + c4]);
            *reinterpret_cast<float4*>(&Cm[(size_t)(bxm * 128 + rp) * ldC + byn * 128 + c4]) = v;
        }
    }
}

// ---- finalize row stats: merge 32 partials -> adj = max + ln(sumexp) -------
__global__ __launch_bounds__(256) void rowfin_kernel() {
    const int warp = threadIdx.x >> 5, lane = threadIdx.x & 31;
    const int n = blockIdx.x * 8 + warp;
    const int b = blockIdx.y;
    const size_t idx = (((size_t)b * NN) + n) * 32 + lane;
    float m = g_pmx[idx], se = g_pse[idx];
    float M = m;
#pragma unroll
    for (int o = 16; o > 0; o >>= 1) M = fmaxf(M, __shfl_xor_sync(~0u, M, o));
    float z = se * __expf(m - M);
#pragma unroll
    for (int o = 16; o > 0; o >>= 1) z += __shfl_xor_sync(~0u, z, o);
    if (lane == 0) g_mx[b * NN + n] = M + __logf(z);
}

// ------- fused x@A GEMM, split-K=4, single-sync: B = exp(S - adj) -----------
// grid (32, 4, NB); byk selects n-range [byk*1024, +1024), partial -> C[byk].
// smem: A stages 3x20480 @0; B stages 2x20480 @61440. Total 100 KB.
__global__ __launch_bounds__(256, 2) void mma_gemm_expB(
    const __half* __restrict__ Ab, size_t planeA,
    const float* __restrict__ S, const float* __restrict__ adjg,
    float* __restrict__ C0, float* __restrict__ C1,
    float* __restrict__ C2, float* __restrict__ C3) {
    extern __shared__ char sm[];
    const int tid = threadIdx.x, lane = tid & 31, wid = tid >> 5;
    const int wm = wid & 1, wn = wid >> 1;
    const int bxm = blockIdx.x, byk = blockIdx.y, b = blockIdx.z;
    const int kbase = byk << 10;
    const __half* Abase = Ab + (size_t)b * 128 * NN + kbase;
    const float* Sbase = S + (size_t)b * NSQ + (size_t)(bxm * 128) * NN + kbase;
    const float* adjb = adjg + (size_t)b * NN + kbase;
    float* Cp = (byk == 0) ? C0 : (byk == 1) ? C1 : (byk == 2) ? C2 : C3;

    float acc[4][4][4];
#pragma unroll
    for (int i = 0; i < 4; i++)
#pragma unroll
        for (int j = 0; j < 4; j++)
#pragma unroll
            for (int r = 0; r < 4; r++) acc[i][j][r] = 0.f;

    const uint32_t smb = smem_u32(sm);
    const uint32_t aoff_rel = (uint32_t)((wm * 64 + (lane & 15)) * 80 + ((lane >> 4) & 1) * 16);
    const uint32_t boff_rel = (uint32_t)((wn * 32 + (lane & 7) + ((lane >> 4) & 1) * 8) * 80 +
                                         ((lane >> 3) & 1) * 16);
    const int f4n = (tid & 7) * 4;

    auto issueA = [&](int kt, int st3) {
        const int k0 = kt << 5;
        const uint32_t sbase = smb + st3 * 20480;
#pragma unroll
        for (int i = tid; i < 1024; i += 256) {
            int pl = i >> 9, rem = i & 511, row = rem >> 2, u = rem & 3;
            const __half* src = Abase + (size_t)pl * planeA + (size_t)row * NN + k0 + u * 8;
            CPASYNC16(sbase + pl * 10240 + row * 80 + u * 16, src);
        }
        CPCOMMIT();
    };
    auto ldgB = [&](int kt, float4* r, float4& a4) {
        const int k0 = kt << 5;
#pragma unroll
        for (int j = 0; j < 4; j++) {
            int row = (tid + j * 256) >> 3;
            r[j] = *reinterpret_cast<const float4*>(Sbase + (size_t)row * NN + k0 + f4n);
        }
        a4 = *reinterpret_cast<const float4*>(adjb + k0 + f4n);
    };

    float4 br[4], adjr;
    ldgB(0, br, adjr);
    issueA(0, 0);
    int a3 = 0;
    const int KT = 32;
    for (int kt = 0; kt < KT; kt++) {
        int an3 = a3 + 1;
        if (an3 == 3) an3 = 0;
        if (kt + 1 < KT) {
            issueA(kt + 1, an3);
            CPWAIT(1);
        } else {
            CPWAIT(0);
        }
        {
            char* bsb = sm + 61440 + (kt & 1) * 20480;
#pragma unroll
            for (int j = 0; j < 4; j++) {
                int idx = tid + j * 256;
                int row = idx >> 3, f4 = idx & 7;
                float4 s4 = br[j];
                float a0 = __expf(s4.x - adjr.x);
                float a1 = __expf(s4.y - adjr.y);
                float a2 = __expf(s4.z - adjr.z);
                float a3v = __expf(s4.w - adjr.w);
                __half h0[4], h1[4];
                split2h(a0, h0[0], h1[0]);
                split2h(a1, h0[1], h1[1]);
                split2h(a2, h0[2], h1[2]);
                split2h(a3v, h0[3], h1[3]);
                union { __half2 h2[2]; uint2 u; } p0, p1;
                p0.h2[0] = __halves2half2(h0[0], h0[1]);
                p0.h2[1] = __halves2half2(h0[2], h0[3]);
                p1.h2[0] = __halves2half2(h1[0], h1[1]);
                p1.h2[1] = __halves2half2(h1[2], h1[3]);
                *reinterpret_cast<uint2*>(bsb + row * 80 + f4 * 8) = p0.u;
                *reinterpret_cast<uint2*>(bsb + 10240 + row * 80 + f4 * 8) = p1.u;
            }
        }
        if (kt + 1 < KT) ldgB(kt + 1, br, adjr);
        __syncthreads();
        const uint32_t aoff = smb + a3 * 20480 + aoff_rel;
        const uint32_t boff = smb + 61440 + (kt & 1) * 20480 + boff_rel;
#pragma unroll
        for (int ks = 0; ks < 2; ks++)
            mma_3term_ks(aoff + ks * 32, boff + ks * 32, acc);
        a3 = an3;
    }
    const int g = lane >> 2, tq = lane & 3;
    float* Cb = Cp + (size_t)b * 128 * NN + (size_t)(bxm * 128 + wn * 32);
#pragma unroll
    for (int am = 0; am < 4; am++) {
        size_t r0 = (size_t)(wm * 64 + am * 16 + g);
#pragma unroll
        for (int an = 0; an < 4; an++) {
            int c = an * 8 + tq * 2;
            *reinterpret_cast<float2*>(&Cb[r0 * NN + c]) =
                make_float2(acc[am][an][0], acc[am][an][1]);
            *reinterpret_cast<float2*>(&Cb[(r0 + 8) * NN + c]) =
                make_float2(acc[am][an][2], acc[am][an][3]);
        }
    }
}

// ------- fused x split: natural fp16x2 planes + transposed fp16x2 planes -----
__global__ __launch_bounds__(256) void xsplit_kernel(const float* __restrict__ src,
                                                     __half* __restrict__ n0,
                                                     __half* __restrict__ n1,
                                                     __half* __restrict__ t0,
                                                     __half* __restrict__ t1) {
    __shared__ float t[32][33];
    const int tx = threadIdx.x & 31, ty = threadIdx.x >> 5;
    const int c0 = blockIdx.x * 32, r0 = blockIdx.y * 32, b = blockIdx.z;
    const float* s = src + (size_t)b * 128 * NN;
    const size_t nbase = (size_t)b * 128 * NN;
#pragma unroll
    for (int i = ty; i < 32; i += 8) {
        float v = s[(size_t)(r0 + i) * NN + c0 + tx];
        t[i][tx] = v;
        __half h0, h1;
        split2h(v, h0, h1);
        size_t o = nbase + (size_t)(r0 + i) * NN + c0 + tx;
        n0[o] = h0;
        n1[o] = h1;
    }
    __syncthreads();
#pragma unroll
    for (int i = ty; i < 32; i += 8) {
        float v = t[tx][i];
        __half h0, h1;
        split2h(v, h0, h1);
        size_t o = nbase + (size_t)(c0 + i) * 128 + r0 + tx;
        t0[o] = h0;
        t1[o] = h1;
    }
}

// -- 64x64-tile SIMT GEMM; B = sum of NSUM arrays; optional BN+relu; stats ----
template <int NSUM, int BN, int STATS>
__global__ __launch_bounds__(256) void gemm64_kernel(
    const float* __restrict__ Am, int lda,
    const float* __restrict__ Bm, const float* __restrict__ Bm2,
    const float* __restrict__ Bm3, const float* __restrict__ Bm4, size_t strideB,
    float* __restrict__ Cm, size_t strideC, int M, int K) {
    __shared__ float As[16][68];
    __shared__ float Bs[16][68];
    __shared__ float sc_s[128], sh_s[128];
    const int tid = threadIdx.x;
    const int tx = tid & 15, ty = tid >> 4;
    const int n0 = blockIdx.x * 64, m0 = blockIdx.y * 64, b = blockIdx.z;
    const float* Bb = Bm + (size_t)b * strideB + n0;
    const float* Bb2 = (NSUM > 1) ? (Bm2 + (size_t)b * strideB + n0) : nullptr;
    const float* Bb3 = (NSUM > 2) ? (Bm3 + (size_t)b * strideB + n0) : nullptr;
    const float* Bb4 = (NSUM > 3) ? (Bm4 + (size_t)b * strideB + n0) : nullptr;
    if (BN) {
        for (int i = tid; i < K; i += 256) {
            sc_s[i] = g_scale[i];
            sh_s[i] = g_shift[i];
        }
        __syncthreads();
    }
    float acc[4][4];
#pragma unroll
    for (int u = 0; u < 4; u++)
#pragma unroll
        for (int v = 0; v < 4; v++) acc[u][v] = 0.f;

    for (int k0 = 0; k0 < K; k0 += 16) {
#pragma unroll
        for (int i = tid; i < 1024; i += 256) {
            int m = i & 63, k = i >> 6;
            As[k][m] = (m0 + m < M) ? Am[(size_t)(m0 + m) * lda + k0 + k] : 0.f;
        }
#pragma unroll
        for (int i = tid; i < 1024; i += 256) {
            int n = i & 63, k = i >> 6;
            size_t off = (size_t)(k0 + k) * NN + n;
            float raw = Bb[off];
            if (NSUM > 1) raw += Bb2[off];
            if (NSUM > 2) raw += Bb3[off];
            if (NSUM > 3) raw += Bb4[off];
            Bs[k][n] = BN ? fmaxf(raw * sc_s[k0 + k] + sh_s[k0 + k], 0.f) : raw;
        }
        __syncthreads();
#pragma unroll
        for (int k = 0; k < 16; k++) {
            float4 av = *reinterpret_cast<const float4*>(&As[k][ty * 4]);
            float4 bv = *reinterpret_cast<const float4*>(&Bs[k][tx * 4]);
            float aa[4] = {av.x, av.y, av.z, av.w};
            float bb2[4] = {bv.x, bv.y, bv.z, bv.w};
#pragma unroll
            for (int u = 0; u < 4; u++)
#pragma unroll
                for (int v = 0; v < 4; v++) acc[u][v] += aa[u] * bb2[v];
        }
        __syncthreads();
    }
    float* Cb = Cm + (size_t)b * strideC + n0;
#pragma unroll
    for (int u = 0; u < 4; u++) {
        int row = m0 + ty * 4 + u;
        if (row < M) {
            float4 o = make_float4(acc[u][0], acc[u][1], acc[u][2], acc[u][3]);
            *reinterpret_cast<float4*>(&Cb[(size_t)row * NN + tx * 4]) = o;
        }
    }
    if (STATS) {
        const int lane = tid & 31;
#pragma unroll
        for (int u = 0; u < 4; u++) {
            int row = m0 + ty * 4 + u;
            float s = acc[u][0] + acc[u][1] + acc[u][2] + acc[u][3];
            float q = acc[u][0] * acc[u][0] + acc[u][1] * acc[u][1] +
                      acc[u][2] * acc[u][2] + acc[u][3] * acc[u][3];
#pragma unroll
            for (int o = 8; o > 0; o >>= 1) {
                s += __shfl_xor_sync(~0u, s, o);
                q += __shfl_xor_sync(~0u, q, o);
            }
            if ((lane & 15) == 0 && row < M) {
                atomicAdd(&g_sums[row], s);
                atomicAdd(&g_sumsq[row], q);
            }
        }
    }
}

// ---------------- zero init ----------------
__global__ __launch_bounds__(256) void zeroM_kernel() {
    for (int i = threadIdx.x + blockIdx.x * 256; i < NB * 32 * 32; i += gridDim.x * 256)
        g_M[i] = 0.f;
}
__global__ __launch_bounds__(128) void zeroStats_kernel() {
    g_sums[threadIdx.x] = 0.f;
    g_sumsq[threadIdx.x] = 0.f;
}

// ---------------- BN scale/shift from stats; re-zero stats ----------------
__global__ void scale_kernel(const float* __restrict__ gw, const float* __restrict__ bw, int Co) {
    const int o = threadIdx.x;
    if (o < Co) {
        const float invM = 1.f / (float)(NB * NN);
        float mean = g_sums[o] * invM;
        float var = g_sumsq[o] * invM - mean * mean;
        float sc = rsqrtf(var + 1e-5f) * gw[o];
        g_scale[o] = sc;
        g_shift[o] = bw[o] - mean * sc;
    }
    __syncthreads();
    g_sums[o] = 0.f;
    g_sumsq[o] = 0.f;
}

// ---------------- BN+relu+fp16 split (layer0 output -> expB input planes) ----
__global__ __launch_bounds__(256) void bnrelu_split_kernel(
    const float* __restrict__ y, __half* __restrict__ d0, __half* __restrict__ d1) {
    const int total = NB * 128 * NN;
    for (int idx = blockIdx.x * blockDim.x + threadIdx.x; idx < total;
         idx += gridDim.x * blockDim.x) {
        int o = (idx >> 12) & 127;
        float v = fmaxf(y[idx] * g_scale[o] + g_shift[o], 0.f);
        __half h0, h1;
        split2h(v, h0, h1);
        d0[idx] = h0;
        d1[idx] = h1;
    }
}

// ---------------- BN + channel softmax (layer3 output -> p) ----------------
__global__ __launch_bounds__(256) void chsoftmax_bn_kernel(const float* __restrict__ yin,
                                                           float* __restrict__ outp) {
    const int n = blockIdx.x * blockDim.x + threadIdx.x;
    const int b = blockIdx.y;
    const size_t base = (size_t)b * 32 * NN + n;
    float v[32];
    float mx = -3.4e38f;
#pragma unroll
    for (int c = 0; c < 32; c++) {
        v[c] = fmaxf(yin[base + (size_t)c * NN] * g_scale[c] + g_shift[c], 0.f);
        mx = fmaxf(mx, v[c]);
    }
    float s = 0.f;
#pragma unroll
    for (int c = 0; c < 32; c++) {
        float e = __expf(v[c] - mx);
        v[c] = e;
        s += e;
    }
    float inv = 1.f / s;
#pragma unroll
    for (int c = 0; c < 32; c++) outp[base + (size_t)c * NN] = v[c] * inv;
}

// ---------------- p p^T / finalize ----------------
__global__ __launch_bounds__(1024) void ppt_kernel(const float* __restrict__ p) {
    __shared__ float sp[32][129];
    const int b = blockIdx.y;
    const int nc = blockIdx.x * 128;
    const int tid = threadIdx.x;
    for (int t = tid; t < 32 * 128; t += 1024) {
        int c = t >> 7, n = t & 127;
        sp[c][n] = p[(size_t)b * 32 * NN + (size_t)c * NN + nc + n];
    }
    __syncthreads();
    const int i = tid >> 5, j = tid & 31;
    float acc = 0.f;
#pragma unroll 8
    for (int n = 0; n < 128; n++) acc += sp[i][n] * sp[j][n];
    atomicAdd(&g_M[b * 1024 + tid], acc);
}

__global__ __launch_bounds__(1024) void finalize_kernel(float* __restrict__ outp) {
    const int b = blockIdx.x;
    const int tid = threadIdx.x;
    float m = g_M[b * 1024 + tid];
    float d = (((tid >> 5) == (tid & 31)) ? 1.f : 0.f) - m;
    __shared__ float red[1024];
    red[tid] = d * d;
    __syncthreads();
    for (int s = 512; s > 0; s >>= 1) {
        if (tid < s) red[tid] += red[tid + s];
        __syncthreads();
    }
    if (tid == 0) outp[(size_t)NB * 32 * NN + b] = sqrtf(red[0]);
}

// ---------------- launch ----------------
extern "C" void kernel_launch(void* const* d_in, const int* in_sizes, int n_in,
                              void* d_out, int out_size) {
    const float* x = (const float*)d_in[0];
    const float *w[4], *g[4], *bb[4];
    if (n_in >= 13 && in_sizes[2] == 128 && in_sizes[3] == 128 && in_sizes[4] == 16384) {
        for (int i = 0; i < 4; i++) {
            w[i] = (const float*)d_in[1 + 3 * i];
            g[i] = (const float*)d_in[2 + 3 * i];
            bb[i] = (const float*)d_in[3 + 3 * i];
        }
    } else {
        for (int i = 0; i < 4; i++) {
            w[i] = (const float*)d_in[1 + i];
            g[i] = (const float*)d_in[5 + i];
            bb[i] = (const float*)d_in[9 + i];
        }
    }
    float* out = (float*)d_out;

    float *A, *T, *Y, *X, *Z, *W, *MX;
    __half *XS, *XT;
    cudaGetSymbolAddress((void**)&A, g_A);
    cudaGetSymbolAddress((void**)&T, g_t);
    cudaGetSymbolAddress((void**)&Y, g_y);
    cudaGetSymbolAddress((void**)&X, g_x);
    cudaGetSymbolAddress((void**)&Z, g_z);
    cudaGetSymbolAddress((void**)&W, g_w);
    cudaGetSymbolAddress((void**)&MX, g_mx);
    cudaGetSymbolAddress((void**)&XS, g_xs);
    cudaGetSymbolAddress((void**)&XT, g_xT);

    cudaFuncSetAttribute(mma_gemm<1>, cudaFuncAttributeMaxDynamicSharedMemorySize, 81920);
    cudaFuncSetAttribute(mma_gemm_expB, cudaFuncAttributeMaxDynamicSharedMemorySize, 102400);

    const size_t sBig = (size_t)128 * NN;
    const size_t pSmall = (size_t)NB * sBig;

    zeroM_kernel<<<16, 256>>>();
    xsplit_kernel<<<dim3(128, 4, NB), 256>>>(x, XS, XS + pSmall, XT, XT + pSmall);
    zeroStats_kernel<<<1, 128>>>();

    // S = x^T x (fp16x3 split mma, symmetric, fused partial softmax stats)
    mma_gemm<1><<<dim3(32, 32, NB), 256, 81920>>>(
        XT, pSmall, 128, (size_t)NN * 128,
        XT, pSmall, 128, (size_t)NN * 128,
        A, NN, NSQ, 128);
    rowfin_kernel<<<dim3(512, NB), 256>>>();

    // layer 0: t = x @ A (fused exp-B, split-K=4 -> T,Y,X,Z) ; y = w0*Σ -> W
    mma_gemm_expB<<<dim3(32, 4, NB), 256, 102400>>>(XS, pSmall, A, MX, T, Y, X, Z);
    gemm64_kernel<4, 0, 1><<<dim3(64, 2, NB), 256>>>(w[0], 128, T, Y, X, Z, sBig, W, sBig, 128, 128);
    scale_kernel<<<1, 128>>>(g[0], bb[0], 128);
    bnrelu_split_kernel<<<2048, 256>>>(W, XS, XS + pSmall);

    // layer 1: t = X @ A (fused exp-B, split-K=4) ; y = w1*Σ -> W
    mma_gemm_expB<<<dim3(32, 4, NB), 256, 102400>>>(XS, pSmall, A, MX, T, Y, X, Z);
    gemm64_kernel<4, 0, 1><<<dim3(64, 2, NB), 256>>>(w[1], 128, T, Y, X, Z, sBig, W, sBig, 128, 128);
    scale_kernel<<<1, 128>>>(g[1], bb[1], 128);

    // layer 2: y = w2 * BN(W) (128->64) -> T
    gemm64_kernel<1, 1, 1><<<dim3(64, 1, NB), 256>>>(w[2], 128, W, nullptr, nullptr, nullptr, sBig, T, (size_t)64 * NN, 64, 128);
    scale_kernel<<<1, 128>>>(g[2], bb[2], 64);

    // layer 3: y = w3 * BN(T) (64->32) -> Y
    gemm64_kernel<1, 1, 1><<<dim3(64, 1, NB), 256>>>(w[3], 64, T, nullptr, nullptr, nullptr, (size_t)64 * NN, Y, (size_t)32 * NN, 32, 64);
    scale_kernel<<<1, 128>>>(g[3], bb[3], 32);

    // p = BN + softmax over channels -> out; l = ||I - p p^T||_F per batch
    chsoftmax_bn_kernel<<<dim3(16, NB), 256>>>(Y, out);
    ppt_kernel<<<dim3(32, NB), 1024>>>(out);
    finalize_kernel<<<NB, 1024>>>(out);
}

// round 16
// speedup vs baseline: 1.1001x; 1.1001x over previous
#include <cuda_runtime.h>
#include <cuda_fp16.h>
#include <math.h>
#include <stdint.h>

#define NB 4
#define NN 4096
#define NSQ ((size_t)NN * (size_t)NN)

// ---------------- scratch (device globals: allocation-free) ----------------
__device__ float g_A[(size_t)NB * NSQ];       // 268 MB: S (gram, symmetric)
__device__ float g_t[(size_t)NB * 128 * NN];  // split-K partial 0 / layer buffers
__device__ float g_y[(size_t)NB * 128 * NN];  // split-K partial 1 / layer buffers
__device__ float g_x[(size_t)NB * 128 * NN];  // conv outputs
__device__ float g_sums[128];
__device__ float g_sumsq[128];
__device__ float g_scale[128];
__device__ float g_shift[128];
__device__ float g_M[NB * 32 * 32];
__device__ float g_mx[NB * NN];                    // per-row adj = max + ln(sumexp)
__device__ float g_pmx[(size_t)NB * NN * 32];      // per-(row, m-tile) partial max
__device__ float g_pse[(size_t)NB * NN * 32];      // per-(row, m-tile) partial sumexp
__device__ __half g_xs[2][(size_t)NB * 128 * NN];  // x / X natural, 2 fp16 planes
__device__ __half g_xT[2][(size_t)NB * NN * 128];  // x transposed, 2 fp16 planes

__device__ __forceinline__ uint32_t smem_u32(const void* p) {
    uint32_t a;
    asm("{ .reg .u64 t; cvta.to.shared.u64 t, %1; cvt.u32.u64 %0, t; }" : "=r"(a) : "l"(p));
    return a;
}

#define LDSM4(r0, r1, r2, r3, addr) \
    asm volatile("ldmatrix.sync.aligned.m8n8.x4.shared.b16 {%0,%1,%2,%3}, [%4];" \
        : "=r"(r0), "=r"(r1), "=r"(r2), "=r"(r3) : "r"(addr))

#define MMAH(d, a, b0, b1) \
    asm volatile("mma.sync.aligned.m16n8k16.row.col.f32.f16.f16.f32 " \
        "{%0,%1,%2,%3},{%4,%5,%6,%7},{%8,%9},{%0,%1,%2,%3};" \
        : "+f"((d)[0]), "+f"((d)[1]), "+f"((d)[2]), "+f"((d)[3]) \
        : "r"((a)[0]), "r"((a)[1]), "r"((a)[2]), "r"((a)[3]), "r"(b0), "r"(b1))

#define CPASYNC16(dst, src) \
    asm volatile("cp.async.cg.shared.global [%0], [%1], 16;" :: "r"(dst), "l"(src))
#define CPCOMMIT() asm volatile("cp.async.commit_group;" ::: "memory")
#define CPWAIT(n)  asm volatile("cp.async.wait_group %0;" :: "n"(n) : "memory")

__device__ __forceinline__ void split2h(float v, __half& h0, __half& h1) {
    h0 = __float2half(v);
    h1 = __float2half(v - __half2float(h0));
}

// Fragment-reuse MMA block for one ks-step: terms (a0,b0), (a0,b1), (a1,b0).
// 12 LDSM4 / 48 MMAs per call.
__device__ __forceinline__ void mma_3term_ks(uint32_t aoff, uint32_t boff,
                                             float acc[4][4][4]) {
    uint32_t aq[4][4], bq0[2][4], bq1[2][4];
#pragma unroll
    for (int am = 0; am < 4; am++)
        LDSM4(aq[am][0], aq[am][1], aq[am][2], aq[am][3], aoff + am * 1280);
#pragma unroll
    for (int np = 0; np < 2; np++)
        LDSM4(bq0[np][0], bq0[np][1], bq0[np][2], bq0[np][3], boff + np * 1280);
#pragma unroll
    for (int am = 0; am < 4; am++)
#pragma unroll
        for (int an = 0; an < 4; an++)
            MMAH(acc[am][an], aq[am], bq0[an >> 1][(an & 1) * 2], bq0[an >> 1][(an & 1) * 2 + 1]);
#pragma unroll
    for (int np = 0; np < 2; np++)
        LDSM4(bq1[np][0], bq1[np][1], bq1[np][2], bq1[np][3], boff + 10240 + np * 1280);
#pragma unroll
    for (int am = 0; am < 4; am++)
#pragma unroll
        for (int an = 0; an < 4; an++)
            MMAH(acc[am][an], aq[am], bq1[an >> 1][(an & 1) * 2], bq1[an >> 1][(an & 1) * 2 + 1]);
#pragma unroll
    for (int am = 0; am < 4; am++)
        LDSM4(aq[am][0], aq[am][1], aq[am][2], aq[am][3], aoff + 10240 + am * 1280);
#pragma unroll
    for (int am = 0; am < 4; am++)
#pragma unroll
        for (int an = 0; an < 4; an++)
            MMAH(acc[am][an], aq[am], bq0[an >> 1][(an & 1) * 2], bq0[an >> 1][(an & 1) * 2 + 1]);
}

// ---------------- mma.sync fp16 split GEMM (gram): D = Aop * Bop^T -----------
template <int SYM>
__global__ __launch_bounds__(256, 2) void mma_gemm(
    const __half* __restrict__ Ab, size_t planeA, size_t pitchA, size_t batchA,
    const __half* __restrict__ Bb, size_t planeB, size_t pitchB, size_t batchB,
    float* __restrict__ C, size_t ldC, size_t batchC, int K) {
    extern __shared__ char sm[];
    constexpr int STAGE = 40960;  // 4 planes x 10240
    const int bxm = blockIdx.x, byn = blockIdx.y, b = blockIdx.z;
    if (SYM && bxm < byn) return;
    const int tid = threadIdx.x, lane = tid & 31, wid = tid >> 5;
    const int wm = wid & 1, wn = wid >> 1;
    const __half* Abase = Ab + (size_t)b * batchA + (size_t)(byn * 128) * pitchA;
    const __half* Bbase = Bb + (size_t)b * batchB + (size_t)(bxm * 128) * pitchB;

    float acc[4][4][4];
#pragma unroll
    for (int i = 0; i < 4; i++)
#pragma unroll
        for (int j = 0; j < 4; j++)
#pragma unroll
            for (int r = 0; r < 4; r++) acc[i][j][r] = 0.f;

    const uint32_t smb = smem_u32(sm);
    const uint32_t aoff_rel = (uint32_t)((wm * 64 + (lane & 15)) * 80 + ((lane >> 4) & 1) * 16);
    const uint32_t boff_rel = 20480u +
                              (uint32_t)((wn * 32 + (lane & 7) + ((lane >> 4) & 1) * 8) * 80 +
                                         ((lane >> 3) & 1) * 16);

    const int KT = K >> 5;
    auto issue = [&](int kt, int buf) {
        const int k0 = kt << 5;
        const uint32_t sbase = smb + buf * STAGE;
#pragma unroll
        for (int i = tid; i < 2048; i += 256) {
            int pl = i >> 9, rem = i & 511, row = rem >> 2, u = rem & 3;
            const __half* src = (pl < 2)
                ? Abase + (size_t)pl * planeA + (size_t)row * pitchA + k0 + u * 8
                : Bbase + (size_t)(pl - 2) * planeB + (size_t)row * pitchB + k0 + u * 8;
            CPASYNC16(sbase + pl * 10240 + row * 80 + u * 16, src);
        }
        CPCOMMIT();
    };

    issue(0, 0);
    int buf = 0;
    for (int kt = 0; kt < KT; kt++) {
        if (kt + 1 < KT) {
            issue(kt + 1, buf ^ 1);
            CPWAIT(1);
        } else {
            CPWAIT(0);
        }
        __syncthreads();
        const uint32_t sb = smb + buf * STAGE;
#pragma unroll
        for (int ks = 0; ks < 2; ks++)
            mma_3term_ks(sb + aoff_rel + ks * 32, sb + boff_rel + ks * 32, acc);
        __syncthreads();
        buf ^= 1;
    }
    const int g = lane >> 2, tq = lane & 3;
    float* Cb = C + (size_t)b * batchC + (size_t)(bxm * 128 + wn * 32);
#pragma unroll
    for (int am = 0; am < 4; am++) {
        size_t r0 = (size_t)(byn * 128 + wm * 64 + am * 16 + g);
#pragma unroll
        for (int an = 0; an < 4; an++) {
            int c = an * 8 + tq * 2;
            *reinterpret_cast<float2*>(&Cb[r0 * ldC + c]) =
                make_float2(acc[am][an][0], acc[am][an][1]);
            *reinterpret_cast<float2*>(&Cb[(r0 + 8) * ldC + c]) =
                make_float2(acc[am][an][2], acc[am][an][3]);
        }
    }
    float* sPM1 = reinterpret_cast<float*>(sm);
    float* sPS1 = reinterpret_cast<float*>(sm + 2048);
    float* sPM2 = reinterpret_cast<float*>(sm + 4096);
    float* sPS2 = reinterpret_cast<float*>(sm + 5120);
    float* st = reinterpret_cast<float*>(sm + 8192);

#pragma unroll
    for (int am = 0; am < 4; am++) {
#pragma unroll
        for (int half = 0; half < 2; half++) {
            float m = -3.4e38f;
#pragma unroll
            for (int an = 0; an < 4; an++)
                m = fmaxf(m, fmaxf(acc[am][an][half * 2], acc[am][an][half * 2 + 1]));
            m = fmaxf(m, __shfl_xor_sync(~0u, m, 1));
            m = fmaxf(m, __shfl_xor_sync(~0u, m, 2));
            float se = 0.f;
#pragma unroll
            for (int an = 0; an < 4; an++)
                se += __expf(acc[am][an][half * 2] - m) + __expf(acc[am][an][half * 2 + 1] - m);
            se += __shfl_xor_sync(~0u, se, 1);
            se += __shfl_xor_sync(~0u, se, 2);
            if (tq == 0) {
                int row = wm * 64 + am * 16 + half * 8 + g;
                sPM1[wn * 128 + row] = m;
                sPS1[wn * 128 + row] = se;
            }
        }
    }
    if (SYM && bxm != byn) {
#pragma unroll
        for (int an = 0; an < 4; an++) {
#pragma unroll
            for (int sub = 0; sub < 2; sub++) {
                float m = -3.4e38f;
#pragma unroll
                for (int am = 0; am < 4; am++)
                    m = fmaxf(m, fmaxf(acc[am][an][sub], acc[am][an][2 + sub]));
                m = fmaxf(m, __shfl_xor_sync(~0u, m, 4));
                m = fmaxf(m, __shfl_xor_sync(~0u, m, 8));
                m = fmaxf(m, __shfl_xor_sync(~0u, m, 16));
                float se = 0.f;
#pragma unroll
                for (int am = 0; am < 4; am++)
                    se += __expf(acc[am][an][sub] - m) + __expf(acc[am][an][2 + sub] - m);
                se += __shfl_xor_sync(~0u, se, 4);
                se += __shfl_xor_sync(~0u, se, 8);
                se += __shfl_xor_sync(~0u, se, 16);
                if (g == 0) {
                    int col = wn * 32 + an * 8 + tq * 2 + sub;
                    sPM2[wm * 128 + col] = m;
                    sPS2[wm * 128 + col] = se;
                }
            }
        }
#pragma unroll
        for (int am = 0; am < 4; am++) {
            int rl = wm * 64 + am * 16 + g;
#pragma unroll
            for (int an = 0; an < 4; an++) {
                int cl = wn * 32 + an * 8 + tq * 2;
                st[(size_t)cl * 132 + rl] = acc[am][an][0];
                st[(size_t)(cl + 1) * 132 + rl] = acc[am][an][1];
                st[(size_t)cl * 132 + rl + 8] = acc[am][an][2];
                st[(size_t)(cl + 1) * 132 + rl + 8] = acc[am][an][3];
            }
        }
    }
    __syncthreads();
    if (tid < 128) {
        float m0 = sPM1[tid], m1 = sPM1[128 + tid], m2 = sPM1[256 + tid], m3 = sPM1[384 + tid];
        float m = fmaxf(fmaxf(m0, m1), fmaxf(m2, m3));
        float se = sPS1[tid] * __expf(m0 - m) + sPS1[128 + tid] * __expf(m1 - m) +
                   sPS1[256 + tid] * __expf(m2 - m) + sPS1[384 + tid] * __expf(m3 - m);
        size_t idx = (((size_t)b * NN) + byn * 128 + tid) * 32 + bxm;
        g_pmx[idx] = m;
        g_pse[idx] = se;
    } else if (SYM && bxm != byn) {
        int r = tid - 128;
        float m0 = sPM2[r], m1 = sPM2[128 + r];
        float m = fmaxf(m0, m1);
        float se = sPS2[r] * __expf(m0 - m) + sPS2[128 + r] * __expf(m1 - m);
        size_t idx = (((size_t)b * NN) + bxm * 128 + r) * 32 + byn;
        g_pmx[idx] = m;
        g_pse[idx] = se;
    }
    if (SYM && bxm != byn) {
        float* Cm = C + (size_t)b * batchC;
        for (int i = tid; i < 4096; i += 256) {
            int rp = i >> 5, c4 = (i & 31) * 4;
            float4 v = *reinterpret_cast<const float4*>(&st[(size_t)rp * 132 + c4]);
            *reinterpret_cast<float4*>(&Cm[(size_t)(bxm * 128 + rp) * ldC + byn * 128 + c4]) = v;
        }
    }
}

// ---- finalize row stats: merge 32 partials -> adj = max + ln(sumexp) -------
__global__ __launch_bounds__(256) void rowfin_kernel() {
    const int warp = threadIdx.x >> 5, lane = threadIdx.x & 31;
    const int n = blockIdx.x * 8 + warp;
    const int b = blockIdx.y;
    const size_t idx = (((size_t)b * NN) + n) * 32 + lane;
    float m = g_pmx[idx], se = g_pse[idx];
    float M = m;
#pragma unroll
    for (int o = 16; o > 0; o >>= 1) M = fmaxf(M, __shfl_xor_sync(~0u, M, o));
    float z = se * __expf(m - M);
#pragma unroll
    for (int o = 16; o > 0; o >>= 1) z += __shfl_xor_sync(~0u, z, o);
    if (lane == 0) g_mx[b * NN + n] = M + __logf(z);
}

// ------- fused x@A GEMM, split-K=2, single-sync: B = exp(S - adj) -----------
// grid (32, 2, NB). smem: A stages 3x20480 @0; B stages 2x20480 @61440.
// Packed convert: cvt.rn.f16x2.f32 pairs + half2->float2 residual path.
__global__ __launch_bounds__(256, 2) void mma_gemm_expB(
    const __half* __restrict__ Ab, size_t planeA,
    const float* __restrict__ S, const float* __restrict__ adjg,
    float* __restrict__ C0, float* __restrict__ C1) {
    extern __shared__ char sm[];
    const int tid = threadIdx.x, lane = tid & 31, wid = tid >> 5;
    const int wm = wid & 1, wn = wid >> 1;
    const int bxm = blockIdx.x, byk = blockIdx.y, b = blockIdx.z;
    const int kbase = byk * 2048;
    const __half* Abase = Ab + (size_t)b * 128 * NN + kbase;
    const float* Sbase = S + (size_t)b * NSQ + (size_t)(bxm * 128) * NN + kbase;
    const float* adjb = adjg + (size_t)b * NN + kbase;
    float* Cp = (byk == 0) ? C0 : C1;

    float acc[4][4][4];
#pragma unroll
    for (int i = 0; i < 4; i++)
#pragma unroll
        for (int j = 0; j < 4; j++)
#pragma unroll
            for (int r = 0; r < 4; r++) acc[i][j][r] = 0.f;

    const uint32_t smb = smem_u32(sm);
    const uint32_t aoff_rel = (uint32_t)((wm * 64 + (lane & 15)) * 80 + ((lane >> 4) & 1) * 16);
    const uint32_t boff_rel = (uint32_t)((wn * 32 + (lane & 7) + ((lane >> 4) & 1) * 8) * 80 +
                                         ((lane >> 3) & 1) * 16);
    const int f4n = (tid & 7) * 4;

    auto issueA = [&](int kt, int st3) {
        const int k0 = kt << 5;
        const uint32_t sbase = smb + st3 * 20480;
#pragma unroll
        for (int i = tid; i < 1024; i += 256) {
            int pl = i >> 9, rem = i & 511, row = rem >> 2, u = rem & 3;
            const __half* src = Abase + (size_t)pl * planeA + (size_t)row * NN + k0 + u * 8;
            CPASYNC16(sbase + pl * 10240 + row * 80 + u * 16, src);
        }
        CPCOMMIT();
    };
    auto ldgB = [&](int kt, float4* r, float4& a4) {
        const int k0 = kt << 5;
#pragma unroll
        for (int j = 0; j < 4; j++) {
            int row = (tid + j * 256) >> 3;
            r[j] = __ldcs(reinterpret_cast<const float4*>(Sbase + (size_t)row * NN + k0 + f4n));
        }
        a4 = *reinterpret_cast<const float4*>(adjb + k0 + f4n);
    };

    float4 br[4], adjr;
    ldgB(0, br, adjr);
    issueA(0, 0);
    int a3 = 0;
    const int KT = 64;
    for (int kt = 0; kt < KT; kt++) {
        int an3 = a3 + 1;
        if (an3 == 3) an3 = 0;
        if (kt + 1 < KT) {
            issueA(kt + 1, an3);
            CPWAIT(1);
        } else {
            CPWAIT(0);
        }
        // convert B(kt) into B stage (kt&1): packed f16x2 conversions
        {
            char* bsb = sm + 61440 + (kt & 1) * 20480;
#pragma unroll
            for (int j = 0; j < 4; j++) {
                int idx = tid + j * 256;
                int row = idx >> 3, f4 = idx & 7;
                float4 s4 = br[j];
                float e0 = __expf(s4.x - adjr.x);
                float e1 = __expf(s4.y - adjr.y);
                float e2 = __expf(s4.z - adjr.z);
                float e3 = __expf(s4.w - adjr.w);
                __half2 p0lo = __floats2half2_rn(e0, e1);   // 1x cvt.rn.f16x2.f32
                __half2 p0hi = __floats2half2_rn(e2, e3);
                float2 f0 = __half22float2(p0lo);
                float2 f1 = __half22float2(p0hi);
                __half2 p1lo = __floats2half2_rn(e0 - f0.x, e1 - f0.y);
                __half2 p1hi = __floats2half2_rn(e2 - f1.x, e3 - f1.y);
                union { __half2 h2[2]; uint2 u; } p0, p1;
                p0.h2[0] = p0lo;
                p0.h2[1] = p0hi;
                p1.h2[0] = p1lo;
                p1.h2[1] = p1hi;
                *reinterpret_cast<uint2*>(bsb + row * 80 + f4 * 8) = p0.u;
                *reinterpret_cast<uint2*>(bsb + 10240 + row * 80 + f4 * 8) = p1.u;
            }
        }
        if (kt + 1 < KT) ldgB(kt + 1, br, adjr);
        __syncthreads();  // A(kt) arrived+visible; B(kt) converted by all warps
        const uint32_t aoff = smb + a3 * 20480 + aoff_rel;
        const uint32_t boff = smb + 61440 + (kt & 1) * 20480 + boff_rel;
#pragma unroll
        for (int ks = 0; ks < 2; ks++)
            mma_3term_ks(aoff + ks * 32, boff + ks * 32, acc);
        a3 = an3;
    }
    const int g = lane >> 2, tq = lane & 3;
    float* Cb = Cp + (size_t)b * 128 * NN + (size_t)(bxm * 128 + wn * 32);
#pragma unroll
    for (int am = 0; am < 4; am++) {
        size_t r0 = (size_t)(wm * 64 + am * 16 + g);
#pragma unroll
        for (int an = 0; an < 4; an++) {
            int c = an * 8 + tq * 2;
            *reinterpret_cast<float2*>(&Cb[r0 * NN + c]) =
                make_float2(acc[am][an][0], acc[am][an][1]);
            *reinterpret_cast<float2*>(&Cb[(r0 + 8) * NN + c]) =
                make_float2(acc[am][an][2], acc[am][an][3]);
        }
    }
}

// ------- fused x split: natural fp16x2 planes + transposed fp16x2 planes -----
__global__ __launch_bounds__(256) void xsplit_kernel(const float* __restrict__ src,
                                                     __half* __restrict__ n0,
                                                     __half* __restrict__ n1,
                                                     __half* __restrict__ t0,
                                                     __half* __restrict__ t1) {
    __shared__ float t[32][33];
    const int tx = threadIdx.x & 31, ty = threadIdx.x >> 5;
    const int c0 = blockIdx.x * 32, r0 = blockIdx.y * 32, b = blockIdx.z;
    const float* s = src + (size_t)b * 128 * NN;
    const size_t nbase = (size_t)b * 128 * NN;
#pragma unroll
    for (int i = ty; i < 32; i += 8) {
        float v = s[(size_t)(r0 + i) * NN + c0 + tx];
        t[i][tx] = v;
        __half h0, h1;
        split2h(v, h0, h1);
        size_t o = nbase + (size_t)(r0 + i) * NN + c0 + tx;
        n0[o] = h0;
        n1[o] = h1;
    }
    __syncthreads();
#pragma unroll
    for (int i = ty; i < 32; i += 8) {
        float v = t[tx][i];
        __half h0, h1;
        split2h(v, h0, h1);
        size_t o = nbase + (size_t)(c0 + i) * 128 + r0 + tx;
        t0[o] = h0;
        t1[o] = h1;
    }
}

// -- 64x64-tile SIMT GEMM; B = Bm (+Bm2 if SUM); optional BN+relu on B; stats --
template <int SUM, int BN, int STATS>
__global__ __launch_bounds__(256) void gemm64_kernel(
    const float* __restrict__ Am, int lda,
    const float* __restrict__ Bm, const float* __restrict__ Bm2, size_t strideB,
    float* __restrict__ Cm, size_t strideC, int M, int K) {
    __shared__ float As[16][68];
    __shared__ float Bs[16][68];
    __shared__ float sc_s[128], sh_s[128];
    const int tid = threadIdx.x;
    const int tx = tid & 15, ty = tid >> 4;
    const int n0 = blockIdx.x * 64, m0 = blockIdx.y * 64, b = blockIdx.z;
    const float* Bb = Bm + (size_t)b * strideB + n0;
    const float* Bb2 = SUM ? (Bm2 + (size_t)b * strideB + n0) : nullptr;
    if (BN) {
        for (int i = tid; i < K; i += 256) {
            sc_s[i] = g_scale[i];
            sh_s[i] = g_shift[i];
        }
        __syncthreads();
    }
    float acc[4][4];
#pragma unroll
    for (int u = 0; u < 4; u++)
#pragma unroll
        for (int v = 0; v < 4; v++) acc[u][v] = 0.f;

    for (int k0 = 0; k0 < K; k0 += 16) {
#pragma unroll
        for (int i = tid; i < 1024; i += 256) {
            int m = i & 63, k = i >> 6;
            As[k][m] = (m0 + m < M) ? Am[(size_t)(m0 + m) * lda + k0 + k] : 0.f;
        }
#pragma unroll
        for (int i = tid; i < 1024; i += 256) {
            int n = i & 63, k = i >> 6;
            size_t off = (size_t)(k0 + k) * NN + n;
            float raw = Bb[off];
            if (SUM) raw += Bb2[off];
            Bs[k][n] = BN ? fmaxf(raw * sc_s[k0 + k] + sh_s[k0 + k], 0.f) : raw;
        }
        __syncthreads();
#pragma unroll
        for (int k = 0; k < 16; k++) {
            float4 av = *reinterpret_cast<const float4*>(&As[k][ty * 4]);
            float4 bv = *reinterpret_cast<const float4*>(&Bs[k][tx * 4]);
            float aa[4] = {av.x, av.y, av.z, av.w};
            float bb2[4] = {bv.x, bv.y, bv.z, bv.w};
#pragma unroll
            for (int u = 0; u < 4; u++)
#pragma unroll
                for (int v = 0; v < 4; v++) acc[u][v] += aa[u] * bb2[v];
        }
        __syncthreads();
    }
    float* Cb = Cm + (size_t)b * strideC + n0;
#pragma unroll
    for (int u = 0; u < 4; u++) {
        int row = m0 + ty * 4 + u;
        if (row < M) {
            float4 o = make_float4(acc[u][0], acc[u][1], acc[u][2], acc[u][3]);
            *reinterpret_cast<float4*>(&Cb[(size_t)row * NN + tx * 4]) = o;
        }
    }
    if (STATS) {
        const int lane = tid & 31;
#pragma unroll
        for (int u = 0; u < 4; u++) {
            int row = m0 + ty * 4 + u;
            float s = acc[u][0] + acc[u][1] + acc[u][2] + acc[u][3];
            float q = acc[u][0] * acc[u][0] + acc[u][1] * acc[u][1] +
                      acc[u][2] * acc[u][2] + acc[u][3] * acc[u][3];
#pragma unroll
            for (int o = 8; o > 0; o >>= 1) {
                s += __shfl_xor_sync(~0u, s, o);
                q += __shfl_xor_sync(~0u, q, o);
            }
            if ((lane & 15) == 0 && row < M) {
                atomicAdd(&g_sums[row], s);
                atomicAdd(&g_sumsq[row], q);
            }
        }
    }
}

// ---------------- zero init ----------------
__global__ __launch_bounds__(256) void zeroM_kernel() {
    for (int i = threadIdx.x + blockIdx.x * 256; i < NB * 32 * 32; i += gridDim.x * 256)
        g_M[i] = 0.f;
}
__global__ __launch_bounds__(128) void zeroStats_kernel() {
    g_sums[threadIdx.x] = 0.f;
    g_sumsq[threadIdx.x] = 0.f;
}

// ---------------- BN scale/shift from stats; re-zero stats ----------------
__global__ void scale_kernel(const float* __restrict__ gw, const float* __restrict__ bw, int Co) {
    const int o = threadIdx.x;
    if (o < Co) {
        const float invM = 1.f / (float)(NB * NN);
        float mean = g_sums[o] * invM;
        float var = g_sumsq[o] * invM - mean * mean;
        float sc = rsqrtf(var + 1e-5f) * gw[o];
        g_scale[o] = sc;
        g_shift[o] = bw[o] - mean * sc;
    }
    __syncthreads();
    g_sums[o] = 0.f;
    g_sumsq[o] = 0.f;
}

// ---------------- BN+relu+fp16 split (layer0 output -> expB input planes) ----
__global__ __launch_bounds__(256) void bnrelu_split_kernel(
    const float* __restrict__ y, __half* __restrict__ d0, __half* __restrict__ d1) {
    const int total = NB * 128 * NN;
    for (int idx = blockIdx.x * blockDim.x + threadIdx.x; idx < total;
         idx += gridDim.x * blockDim.x) {
        int o = (idx >> 12) & 127;
        float v = fmaxf(y[idx] * g_scale[o] + g_shift[o], 0.f);
        __half h0, h1;
        split2h(v, h0, h1);
        d0[idx] = h0;
        d1[idx] = h1;
    }
}

// ---------------- BN + channel softmax (layer3 output -> p) ----------------
__global__ __launch_bounds__(256) void chsoftmax_bn_kernel(const float* __restrict__ yin,
                                                           float* __restrict__ outp) {
    const int n = blockIdx.x * blockDim.x + threadIdx.x;
    const int b = blockIdx.y;
    const size_t base = (size_t)b * 32 * NN + n;
    float v[32];
    float mx = -3.4e38f;
#pragma unroll
    for (int c = 0; c < 32; c++) {
        v[c] = fmaxf(yin[base + (size_t)c * NN] * g_scale[c] + g_shift[c], 0.f);
        mx = fmaxf(mx, v[c]);
    }
    float s = 0.f;
#pragma unroll
    for (int c = 0; c < 32; c++) {
        float e = __expf(v[c] - mx);
        v[c] = e;
        s += e;
    }
    float inv = 1.f / s;
#pragma unroll
    for (int c = 0; c < 32; c++) outp[base + (size_t)c * NN] = v[c] * inv;
}

// ---------------- p p^T / finalize ----------------
__global__ __launch_bounds__(1024) void ppt_kernel(const float* __restrict__ p) {
    __shared__ float sp[32][129];
    const int b = blockIdx.y;
    const int nc = blockIdx.x * 128;
    const int tid = threadIdx.x;
    for (int t = tid; t < 32 * 128; t += 1024) {
        int c = t >> 7, n = t & 127;
        sp[c][n] = p[(size_t)b * 32 * NN + (size_t)c * NN + nc + n];
    }
    __syncthreads();
    const int i = tid >> 5, j = tid & 31;
    float acc = 0.f;
#pragma unroll 8
    for (int n = 0; n < 128; n++) acc += sp[i][n] * sp[j][n];
    atomicAdd(&g_M[b * 1024 + tid], acc);
}

__global__ __launch_bounds__(1024) void finalize_kernel(float* __restrict__ outp) {
    const int b = blockIdx.x;
    const int tid = threadIdx.x;
    float m = g_M[b * 1024 + tid];
    float d = (((tid >> 5) == (tid & 31)) ? 1.f : 0.f) - m;
    __shared__ float red[1024];
    red[tid] = d * d;
    __syncthreads();
    for (int s = 512; s > 0; s >>= 1) {
        if (tid < s) red[tid] += red[tid + s];
        __syncthreads();
    }
    if (tid == 0) outp[(size_t)NB * 32 * NN + b] = sqrtf(red[0]);
}

// ---------------- launch ----------------
extern "C" void kernel_launch(void* const* d_in, const int* in_sizes, int n_in,
                              void* d_out, int out_size) {
    const float* x = (const float*)d_in[0];
    const float *w[4], *g[4], *bb[4];
    if (n_in >= 13 && in_sizes[2] == 128 && in_sizes[3] == 128 && in_sizes[4] == 16384) {
        for (int i = 0; i < 4; i++) {
            w[i] = (const float*)d_in[1 + 3 * i];
            g[i] = (const float*)d_in[2 + 3 * i];
            bb[i] = (const float*)d_in[3 + 3 * i];
        }
    } else {
        for (int i = 0; i < 4; i++) {
            w[i] = (const float*)d_in[1 + i];
            g[i] = (const float*)d_in[5 + i];
            bb[i] = (const float*)d_in[9 + i];
        }
    }
    float* out = (float*)d_out;

    float *A, *T, *Y, *X, *MX;
    __half *XS, *XT;
    cudaGetSymbolAddress((void**)&A, g_A);
    cudaGetSymbolAddress((void**)&T, g_t);
    cudaGetSymbolAddress((void**)&Y, g_y);
    cudaGetSymbolAddress((void**)&X, g_x);
    cudaGetSymbolAddress((void**)&MX, g_mx);
    cudaGetSymbolAddress((void**)&XS, g_xs);
    cudaGetSymbolAddress((void**)&XT, g_xT);

    cudaFuncSetAttribute(mma_gemm<1>, cudaFuncAttributeMaxDynamicSharedMemorySize, 81920);
    cudaFuncSetAttribute(mma_gemm_expB, cudaFuncAttributeMaxDynamicSharedMemorySize, 102400);

    const size_t sBig = (size_t)128 * NN;
    const size_t pSmall = (size_t)NB * sBig;

    zeroM_kernel<<<16, 256>>>();
    xsplit_kernel<<<dim3(128, 4, NB), 256>>>(x, XS, XS + pSmall, XT, XT + pSmall);
    zeroStats_kernel<<<1, 128>>>();

    // S = x^T x (fp16x3 split mma, symmetric, fused partial softmax stats)
    mma_gemm<1><<<dim3(32, 32, NB), 256, 81920>>>(
        XT, pSmall, 128, (size_t)NN * 128,
        XT, pSmall, 128, (size_t)NN * 128,
        A, NN, NSQ, 128);
    rowfin_kernel<<<dim3(512, NB), 256>>>();

    // layer 0: t = x @ A (fused exp-B, split-K=2 -> T,Y) ; y = w0*(T+Y) -> X
    mma_gemm_expB<<<dim3(32, 2, NB), 256, 102400>>>(XS, pSmall, A, MX, T, Y);
    gemm64_kernel<1, 0, 1><<<dim3(64, 2, NB), 256>>>(w[0], 128, T, Y, sBig, X, sBig, 128, 128);
    scale_kernel<<<1, 128>>>(g[0], bb[0], 128);
    bnrelu_split_kernel<<<2048, 256>>>(X, XS, XS + pSmall);

    // layer 1: t = X @ A (fused exp-B, split-K=2 -> T,Y) ; y = w1*(T+Y) -> X
    mma_gemm_expB<<<dim3(32, 2, NB), 256, 102400>>>(XS, pSmall, A, MX, T, Y);
    gemm64_kernel<1, 0, 1><<<dim3(64, 2, NB), 256>>>(w[1], 128, T, Y, sBig, X, sBig, 128, 128);
    scale_kernel<<<1, 128>>>(g[1], bb[1], 128);

    // layer 2: y = w2 * BN(X) (128->64) -> T
    gemm64_kernel<0, 1, 1><<<dim3(64, 1, NB), 256>>>(w[2], 128, X, nullptr, sBig, T, (size_t)64 * NN, 64, 128);
    scale_kernel<<<1, 128>>>(g[2], bb[2], 64);

    // layer 3: y = w3 * BN(T) (64->32) -> Y
    gemm64_kernel<0, 1, 1><<<dim3(64, 1, NB), 256>>>(w[3], 64, T, nullptr, (size_t)64 * NN, Y, (size_t)32 * NN, 32, 64);
    scale_kernel<<<1, 128>>>(g[3], bb[3], 32);

    // p = BN + softmax over channels -> out; l = ||I - p p^T||_F per batch
    chsoftmax_bn_kernel<<<dim3(16, NB), 256>>>(Y, out);
    ppt_kernel<<<dim3(32, NB), 1024>>>(out);
    finalize_kernel<<<NB, 1024>>>(out);
}

// round 17
// speedup vs baseline: 1.1039x; 1.0034x over previous
#include <cuda_runtime.h>
#include <cuda_fp16.h>
#include <math.h>
#include <stdint.h>

#define NB 4
#define NN 4096
#define NSQ ((size_t)NN * (size_t)NN)

// ---------------- scratch (device globals: allocation-free) ----------------
__device__ float g_A[(size_t)NB * NSQ];       // 268 MB: S (gram, symmetric)
__device__ float g_t[(size_t)NB * 128 * NN];  // split-K partial 0 / layer buffers
__device__ float g_y[(size_t)NB * 128 * NN];  // split-K partial 1 / layer buffers
__device__ float g_x[(size_t)NB * 128 * NN];  // conv outputs
__device__ float g_sums[128];
__device__ float g_sumsq[128];
__device__ float g_scale[128];
__device__ float g_shift[128];
__device__ float g_M[NB * 32 * 32];
__device__ float g_mx[NB * NN];                    // per-row adj = max + ln(sumexp)
__device__ float g_pmx[(size_t)NB * NN * 32];      // per-(row, m-tile) partial max
__device__ float g_pse[(size_t)NB * NN * 32];      // per-(row, m-tile) partial sumexp
__device__ __half g_xs[2][(size_t)NB * 128 * NN];  // x / X natural, 2 fp16 planes
__device__ __half g_xT[2][(size_t)NB * NN * 128];  // x transposed, 2 fp16 planes

__device__ __forceinline__ uint32_t smem_u32(const void* p) {
    uint32_t a;
    asm("{ .reg .u64 t; cvta.to.shared.u64 t, %1; cvt.u32.u64 %0, t; }" : "=r"(a) : "l"(p));
    return a;
}

#define LDSM4(r0, r1, r2, r3, addr) \
    asm volatile("ldmatrix.sync.aligned.m8n8.x4.shared.b16 {%0,%1,%2,%3}, [%4];" \
        : "=r"(r0), "=r"(r1), "=r"(r2), "=r"(r3) : "r"(addr))

#define MMAH(d, a, b0, b1) \
    asm volatile("mma.sync.aligned.m16n8k16.row.col.f32.f16.f16.f32 " \
        "{%0,%1,%2,%3},{%4,%5,%6,%7},{%8,%9},{%0,%1,%2,%3};" \
        : "+f"((d)[0]), "+f"((d)[1]), "+f"((d)[2]), "+f"((d)[3]) \
        : "r"((a)[0]), "r"((a)[1]), "r"((a)[2]), "r"((a)[3]), "r"(b0), "r"(b1))

#define CPASYNC16(dst, src) \
    asm volatile("cp.async.cg.shared.global [%0], [%1], 16;" :: "r"(dst), "l"(src))
#define CPCOMMIT() asm volatile("cp.async.commit_group;" ::: "memory")
#define CPWAIT(n)  asm volatile("cp.async.wait_group %0;" :: "n"(n) : "memory")

__device__ __forceinline__ void split2h(float v, __half& h0, __half& h1) {
    h0 = __float2half(v);
    h1 = __float2half(v - __half2float(h0));
}

// Fragment-PIPELINED MMA block for one ks-step.
// Terms (a0,b0), (a0,b1), (a1,b0). LDSM schedule hides latency:
//   LDSM a0,b0,b1 -> MMA t0 -> LDSM a1 (separate regs) -> MMA t1 -> MMA t2.
// t1 uses b1 (loaded long before); a1's flight is covered by t1's 16 MMAs.
__device__ __forceinline__ void mma_3term_ks(uint32_t aoff, uint32_t boff,
                                             float acc[4][4][4]) {
    uint32_t aq0[4][4], aq1[4][4], bq0[2][4], bq1[2][4];
#pragma unroll
    for (int am = 0; am < 4; am++)
        LDSM4(aq0[am][0], aq0[am][1], aq0[am][2], aq0[am][3], aoff + am * 1280);
#pragma unroll
    for (int np = 0; np < 2; np++)
        LDSM4(bq0[np][0], bq0[np][1], bq0[np][2], bq0[np][3], boff + np * 1280);
#pragma unroll
    for (int np = 0; np < 2; np++)
        LDSM4(bq1[np][0], bq1[np][1], bq1[np][2], bq1[np][3], boff + 10240 + np * 1280);
    // t0 = a0 x b0
#pragma unroll
    for (int am = 0; am < 4; am++)
#pragma unroll
        for (int an = 0; an < 4; an++)
            MMAH(acc[am][an], aq0[am], bq0[an >> 1][(an & 1) * 2], bq0[an >> 1][(an & 1) * 2 + 1]);
    // prefetch a1 while t1 executes
#pragma unroll
    for (int am = 0; am < 4; am++)
        LDSM4(aq1[am][0], aq1[am][1], aq1[am][2], aq1[am][3], aoff + 10240 + am * 1280);
    // t1 = a0 x b1
#pragma unroll
    for (int am = 0; am < 4; am++)
#pragma unroll
        for (int an = 0; an < 4; an++)
            MMAH(acc[am][an], aq0[am], bq1[an >> 1][(an & 1) * 2], bq1[an >> 1][(an & 1) * 2 + 1]);
    // t2 = a1 x b0
#pragma unroll
    for (int am = 0; am < 4; am++)
#pragma unroll
        for (int an = 0; an < 4; an++)
            MMAH(acc[am][an], aq1[am], bq0[an >> 1][(an & 1) * 2], bq0[an >> 1][(an & 1) * 2 + 1]);
}

// ---------------- mma.sync fp16 split GEMM (gram): D = Aop * Bop^T -----------
template <int SYM>
__global__ __launch_bounds__(256, 2) void mma_gemm(
    const __half* __restrict__ Ab, size_t planeA, size_t pitchA, size_t batchA,
    const __half* __restrict__ Bb, size_t planeB, size_t pitchB, size_t batchB,
    float* __restrict__ C, size_t ldC, size_t batchC, int K) {
    extern __shared__ char sm[];
    constexpr int STAGE = 40960;  // 4 planes x 10240
    const int bxm = blockIdx.x, byn = blockIdx.y, b = blockIdx.z;
    if (SYM && bxm < byn) return;
    const int tid = threadIdx.x, lane = tid & 31, wid = tid >> 5;
    const int wm = wid & 1, wn = wid >> 1;
    const __half* Abase = Ab + (size_t)b * batchA + (size_t)(byn * 128) * pitchA;
    const __half* Bbase = Bb + (size_t)b * batchB + (size_t)(bxm * 128) * pitchB;

    float acc[4][4][4];
#pragma unroll
    for (int i = 0; i < 4; i++)
#pragma unroll
        for (int j = 0; j < 4; j++)
#pragma unroll
            for (int r = 0; r < 4; r++) acc[i][j][r] = 0.f;

    const uint32_t smb = smem_u32(sm);
    const uint32_t aoff_rel = (uint32_t)((wm * 64 + (lane & 15)) * 80 + ((lane >> 4) & 1) * 16);
    const uint32_t boff_rel = 20480u +
                              (uint32_t)((wn * 32 + (lane & 7) + ((lane >> 4) & 1) * 8) * 80 +
                                         ((lane >> 3) & 1) * 16);

    const int KT = K >> 5;
    auto issue = [&](int kt, int buf) {
        const int k0 = kt << 5;
        const uint32_t sbase = smb + buf * STAGE;
#pragma unroll
        for (int i = tid; i < 2048; i += 256) {
            int pl = i >> 9, rem = i & 511, row = rem >> 2, u = rem & 3;
            const __half* src = (pl < 2)
                ? Abase + (size_t)pl * planeA + (size_t)row * pitchA + k0 + u * 8
                : Bbase + (size_t)(pl - 2) * planeB + (size_t)row * pitchB + k0 + u * 8;
            CPASYNC16(sbase + pl * 10240 + row * 80 + u * 16, src);
        }
        CPCOMMIT();
    };

    issue(0, 0);
    int buf = 0;
    for (int kt = 0; kt < KT; kt++) {
        if (kt + 1 < KT) {
            issue(kt + 1, buf ^ 1);
            CPWAIT(1);
        } else {
            CPWAIT(0);
        }
        __syncthreads();
        const uint32_t sb = smb + buf * STAGE;
#pragma unroll
        for (int ks = 0; ks < 2; ks++)
            mma_3term_ks(sb + aoff_rel + ks * 32, sb + boff_rel + ks * 32, acc);
        __syncthreads();
        buf ^= 1;
    }
    const int g = lane >> 2, tq = lane & 3;
    float* Cb = C + (size_t)b * batchC + (size_t)(bxm * 128 + wn * 32);
#pragma unroll
    for (int am = 0; am < 4; am++) {
        size_t r0 = (size_t)(byn * 128 + wm * 64 + am * 16 + g);
#pragma unroll
        for (int an = 0; an < 4; an++) {
            int c = an * 8 + tq * 2;
            *reinterpret_cast<float2*>(&Cb[r0 * ldC + c]) =
                make_float2(acc[am][an][0], acc[am][an][1]);
            *reinterpret_cast<float2*>(&Cb[(r0 + 8) * ldC + c]) =
                make_float2(acc[am][an][2], acc[am][an][3]);
        }
    }
    float* sPM1 = reinterpret_cast<float*>(sm);
    float* sPS1 = reinterpret_cast<float*>(sm + 2048);
    float* sPM2 = reinterpret_cast<float*>(sm + 4096);
    float* sPS2 = reinterpret_cast<float*>(sm + 5120);
    float* st = reinterpret_cast<float*>(sm + 8192);

#pragma unroll
    for (int am = 0; am < 4; am++) {
#pragma unroll
        for (int half = 0; half < 2; half++) {
            float m = -3.4e38f;
#pragma unroll
            for (int an = 0; an < 4; an++)
                m = fmaxf(m, fmaxf(acc[am][an][half * 2], acc[am][an][half * 2 + 1]));
            m = fmaxf(m, __shfl_xor_sync(~0u, m, 1));
            m = fmaxf(m, __shfl_xor_sync(~0u, m, 2));
            float se = 0.f;
#pragma unroll
            for (int an = 0; an < 4; an++)
                se += __expf(acc[am][an][half * 2] - m) + __expf(acc[am][an][half * 2 + 1] - m);
            se += __shfl_xor_sync(~0u, se, 1);
            se += __shfl_xor_sync(~0u, se, 2);
            if (tq == 0) {
                int row = wm * 64 + am * 16 + half * 8 + g;
                sPM1[wn * 128 + row] = m;
                sPS1[wn * 128 + row] = se;
            }
        }
    }
    if (SYM && bxm != byn) {
#pragma unroll
        for (int an = 0; an < 4; an++) {
#pragma unroll
            for (int sub = 0; sub < 2; sub++) {
                float m = -3.4e38f;
#pragma unroll
                for (int am = 0; am < 4; am++)
                    m = fmaxf(m, fmaxf(acc[am][an][sub], acc[am][an][2 + sub]));
                m = fmaxf(m, __shfl_xor_sync(~0u, m, 4));
                m = fmaxf(m, __shfl_xor_sync(~0u, m, 8));
                m = fmaxf(m, __shfl_xor_sync(~0u, m, 16));
                float se = 0.f;
#pragma unroll
                for (int am = 0; am < 4; am++)
                    se += __expf(acc[am][an][sub] - m) + __expf(acc[am][an][2 + sub] - m);
                se += __shfl_xor_sync(~0u, se, 4);
                se += __shfl_xor_sync(~0u, se, 8);
                se += __shfl_xor_sync(~0u, se, 16);
                if (g == 0) {
                    int col = wn * 32 + an * 8 + tq * 2 + sub;
                    sPM2[wm * 128 + col] = m;
                    sPS2[wm * 128 + col] = se;
                }
            }
        }
#pragma unroll
        for (int am = 0; am < 4; am++) {
            int rl = wm * 64 + am * 16 + g;
#pragma unroll
            for (int an = 0; an < 4; an++) {
                int cl = wn * 32 + an * 8 + tq * 2;
                st[(size_t)cl * 132 + rl] = acc[am][an][0];
                st[(size_t)(cl + 1) * 132 + rl] = acc[am][an][1];
                st[(size_t)cl * 132 + rl + 8] = acc[am][an][2];
                st[(size_t)(cl + 1) * 132 + rl + 8] = acc[am][an][3];
            }
        }
    }
    __syncthreads();
    if (tid < 128) {
        float m0 = sPM1[tid], m1 = sPM1[128 + tid], m2 = sPM1[256 + tid], m3 = sPM1[384 + tid];
        float m = fmaxf(fmaxf(m0, m1), fmaxf(m2, m3));
        float se = sPS1[tid] * __expf(m0 - m) + sPS1[128 + tid] * __expf(m1 - m) +
                   sPS1[256 + tid] * __expf(m2 - m) + sPS1[384 + tid] * __expf(m3 - m);
        size_t idx = (((size_t)b * NN) + byn * 128 + tid) * 32 + bxm;
        g_pmx[idx] = m;
        g_pse[idx] = se;
    } else if (SYM && bxm != byn) {
        int r = tid - 128;
        float m0 = sPM2[r], m1 = sPM2[128 + r];
        float m = fmaxf(m0, m1);
        float se = sPS2[r] * __expf(m0 - m) + sPS2[128 + r] * __expf(m1 - m);
        size_t idx = (((size_t)b * NN) + bxm * 128 + r) * 32 + byn;
        g_pmx[idx] = m;
        g_pse[idx] = se;
    }
    if (SYM && bxm != byn) {
        float* Cm = C + (size_t)b * batchC;
        for (int i = tid; i < 4096; i += 256) {
            int rp = i >> 5, c4 = (i & 31) * 4;
            float4 v = *reinterpret_cast<const float4*>(&st[(size_t)rp * 132 + c4]);
            *reinterpret_cast<float4*>(&Cm[(size_t)(bxm * 128 + rp) * ldC + byn * 128 + c4]) = v;
        }
    }
}

// ---- finalize row stats: merge 32 partials -> adj = max + ln(sumexp) -------
__global__ __launch_bounds__(256) void rowfin_kernel() {
    const int warp = threadIdx.x >> 5, lane = threadIdx.x & 31;
    const int n = blockIdx.x * 8 + warp;
    const int b = blockIdx.y;
    const size_t idx = (((size_t)b * NN) + n) * 32 + lane;
    float m = g_pmx[idx], se = g_pse[idx];
    float M = m;
#pragma unroll
    for (int o = 16; o > 0; o >>= 1) M = fmaxf(M, __shfl_xor_sync(~0u, M, o));
    float z = se * __expf(m - M);
#pragma unroll
    for (int o = 16; o > 0; o >>= 1) z += __shfl_xor_sync(~0u, z, o);
    if (lane == 0) g_mx[b * NN + n] = M + __logf(z);
}

// ------- fused x@A GEMM, split-K=2, single-sync: B = exp(S - adj) -----------
__global__ __launch_bounds__(256, 2) void mma_gemm_expB(
    const __half* __restrict__ Ab, size_t planeA,
    const float* __restrict__ S, const float* __restrict__ adjg,
    float* __restrict__ C0, float* __restrict__ C1) {
    extern __shared__ char sm[];
    const int tid = threadIdx.x, lane = tid & 31, wid = tid >> 5;
    const int wm = wid & 1, wn = wid >> 1;
    const int bxm = blockIdx.x, byk = blockIdx.y, b = blockIdx.z;
    const int kbase = byk * 2048;
    const __half* Abase = Ab + (size_t)b * 128 * NN + kbase;
    const float* Sbase = S + (size_t)b * NSQ + (size_t)(bxm * 128) * NN + kbase;
    const float* adjb = adjg + (size_t)b * NN + kbase;
    float* Cp = (byk == 0) ? C0 : C1;

    float acc[4][4][4];
#pragma unroll
    for (int i = 0; i < 4; i++)
#pragma unroll
        for (int j = 0; j < 4; j++)
#pragma unroll
            for (int r = 0; r < 4; r++) acc[i][j][r] = 0.f;

    const uint32_t smb = smem_u32(sm);
    const uint32_t aoff_rel = (uint32_t)((wm * 64 + (lane & 15)) * 80 + ((lane >> 4) & 1) * 16);
    const uint32_t boff_rel = (uint32_t)((wn * 32 + (lane & 7) + ((lane >> 4) & 1) * 8) * 80 +
                                         ((lane >> 3) & 1) * 16);
    const int f4n = (tid & 7) * 4;

    auto issueA = [&](int kt, int st3) {
        const int k0 = kt << 5;
        const uint32_t sbase = smb + st3 * 20480;
#pragma unroll
        for (int i = tid; i < 1024; i += 256) {
            int pl = i >> 9, rem = i & 511, row = rem >> 2, u = rem & 3;
            const __half* src = Abase + (size_t)pl * planeA + (size_t)row * NN + k0 + u * 8;
            CPASYNC16(sbase + pl * 10240 + row * 80 + u * 16, src);
        }
        CPCOMMIT();
    };
    auto ldgB = [&](int kt, float4* r, float4& a4) {
        const int k0 = kt << 5;
#pragma unroll
        for (int j = 0; j < 4; j++) {
            int row = (tid + j * 256) >> 3;
            r[j] = __ldcs(reinterpret_cast<const float4*>(Sbase + (size_t)row * NN + k0 + f4n));
        }
        a4 = *reinterpret_cast<const float4*>(adjb + k0 + f4n);
    };

    float4 br[4], adjr;
    ldgB(0, br, adjr);
    issueA(0, 0);
    int a3 = 0;
    const int KT = 64;
    for (int kt = 0; kt < KT; kt++) {
        int an3 = a3 + 1;
        if (an3 == 3) an3 = 0;
        if (kt + 1 < KT) {
            issueA(kt + 1, an3);
            CPWAIT(1);
        } else {
            CPWAIT(0);
        }
        {
            char* bsb = sm + 61440 + (kt & 1) * 20480;
#pragma unroll
            for (int j = 0; j < 4; j++) {
                int idx = tid + j * 256;
                int row = idx >> 3, f4 = idx & 7;
                float4 s4 = br[j];
                float e0 = __expf(s4.x - adjr.x);
                float e1 = __expf(s4.y - adjr.y);
                float e2 = __expf(s4.z - adjr.z);
                float e3 = __expf(s4.w - adjr.w);
                __half2 p0lo = __floats2half2_rn(e0, e1);
                __half2 p0hi = __floats2half2_rn(e2, e3);
                float2 f0 = __half22float2(p0lo);
                float2 f1 = __half22float2(p0hi);
                __half2 p1lo = __floats2half2_rn(e0 - f0.x, e1 - f0.y);
                __half2 p1hi = __floats2half2_rn(e2 - f1.x, e3 - f1.y);
                union { __half2 h2[2]; uint2 u; } p0, p1;
                p0.h2[0] = p0lo;
                p0.h2[1] = p0hi;
                p1.h2[0] = p1lo;
                p1.h2[1] = p1hi;
                *reinterpret_cast<uint2*>(bsb + row * 80 + f4 * 8) = p0.u;
                *reinterpret_cast<uint2*>(bsb + 10240 + row * 80 + f4 * 8) = p1.u;
            }
        }
        if (kt + 1 < KT) ldgB(kt + 1, br, adjr);
        __syncthreads();
        const uint32_t aoff = smb + a3 * 20480 + aoff_rel;
        const uint32_t boff = smb + 61440 + (kt & 1) * 20480 + boff_rel;
#pragma unroll
        for (int ks = 0; ks < 2; ks++)
            mma_3term_ks(aoff + ks * 32, boff + ks * 32, acc);
        a3 = an3;
    }
    const int g = lane >> 2, tq = lane & 3;
    float* Cb = Cp + (size_t)b * 128 * NN + (size_t)(bxm * 128 + wn * 32);
#pragma unroll
    for (int am = 0; am < 4; am++) {
        size_t r0 = (size_t)(wm * 64 + am * 16 + g);
#pragma unroll
        for (int an = 0; an < 4; an++) {
            int c = an * 8 + tq * 2;
            *reinterpret_cast<float2*>(&Cb[r0 * NN + c]) =
                make_float2(acc[am][an][0], acc[am][an][1]);
            *reinterpret_cast<float2*>(&Cb[(r0 + 8) * NN + c]) =
                make_float2(acc[am][an][2], acc[am][an][3]);
        }
    }
}

// ------- fused x split: natural fp16x2 planes + transposed fp16x2 planes -----
__global__ __launch_bounds__(256) void xsplit_kernel(const float* __restrict__ src,
                                                     __half* __restrict__ n0,
                                                     __half* __restrict__ n1,
                                                     __half* __restrict__ t0,
                                                     __half* __restrict__ t1) {
    __shared__ float t[32][33];
    const int tx = threadIdx.x & 31, ty = threadIdx.x >> 5;
    const int c0 = blockIdx.x * 32, r0 = blockIdx.y * 32, b = blockIdx.z;
    const float* s = src + (size_t)b * 128 * NN;
    const size_t nbase = (size_t)b * 128 * NN;
#pragma unroll
    for (int i = ty; i < 32; i += 8) {
        float v = s[(size_t)(r0 + i) * NN + c0 + tx];
        t[i][tx] = v;
        __half h0, h1;
        split2h(v, h0, h1);
        size_t o = nbase + (size_t)(r0 + i) * NN + c0 + tx;
        n0[o] = h0;
        n1[o] = h1;
    }
    __syncthreads();
#pragma unroll
    for (int i = ty; i < 32; i += 8) {
        float v = t[tx][i];
        __half h0, h1;
        split2h(v, h0, h1);
        size_t o = nbase + (size_t)(c0 + i) * 128 + r0 + tx;
        t0[o] = h0;
        t1[o] = h1;
    }
}

// -- 64x64-tile SIMT GEMM; B = Bm (+Bm2 if SUM); optional BN+relu on B; stats --
template <int SUM, int BN, int STATS>
__global__ __launch_bounds__(256) void gemm64_kernel(
    const float* __restrict__ Am, int lda,
    const float* __restrict__ Bm, const float* __restrict__ Bm2, size_t strideB,
    float* __restrict__ Cm, size_t strideC, int M, int K) {
    __shared__ float As[16][68];
    __shared__ float Bs[16][68];
    __shared__ float sc_s[128], sh_s[128];
    const int tid = threadIdx.x;
    const int tx = tid & 15, ty = tid >> 4;
    const int n0 = blockIdx.x * 64, m0 = blockIdx.y * 64, b = blockIdx.z;
    const float* Bb = Bm + (size_t)b * strideB + n0;
    const float* Bb2 = SUM ? (Bm2 + (size_t)b * strideB + n0) : nullptr;
    if (BN) {
        for (int i = tid; i < K; i += 256) {
            sc_s[i] = g_scale[i];
            sh_s[i] = g_shift[i];
        }
        __syncthreads();
    }
    float acc[4][4];
#pragma unroll
    for (int u = 0; u < 4; u++)
#pragma unroll
        for (int v = 0; v < 4; v++) acc[u][v] = 0.f;

    for (int k0 = 0; k0 < K; k0 += 16) {
#pragma unroll
        for (int i = tid; i < 1024; i += 256) {
            int m = i & 63, k = i >> 6;
            As[k][m] = (m0 + m < M) ? Am[(size_t)(m0 + m) * lda + k0 + k] : 0.f;
        }
#pragma unroll
        for (int i = tid; i < 1024; i += 256) {
            int n = i & 63, k = i >> 6;
            size_t off = (size_t)(k0 + k) * NN + n;
            float raw = Bb[off];
            if (SUM) raw += Bb2[off];
            Bs[k][n] = BN ? fmaxf(raw * sc_s[k0 + k] + sh_s[k0 + k], 0.f) : raw;
        }
        __syncthreads();
#pragma unroll
        for (int k = 0; k < 16; k++) {
            float4 av = *reinterpret_cast<const float4*>(&As[k][ty * 4]);
            float4 bv = *reinterpret_cast<const float4*>(&Bs[k][tx * 4]);
            float aa[4] = {av.x, av.y, av.z, av.w};
            float bb2[4] = {bv.x, bv.y, bv.z, bv.w};
#pragma unroll
            for (int u = 0; u < 4; u++)
#pragma unroll
                for (int v = 0; v < 4; v++) acc[u][v] += aa[u] * bb2[v];
        }
        __syncthreads();
    }
    float* Cb = Cm + (size_t)b * strideC + n0;
#pragma unroll
    for (int u = 0; u < 4; u++) {
        int row = m0 + ty * 4 + u;
        if (row < M) {
            float4 o = make_float4(acc[u][0], acc[u][1], acc[u][2], acc[u][3]);
            *reinterpret_cast<float4*>(&Cb[(size_t)row * NN + tx * 4]) = o;
        }
    }
    if (STATS) {
        const int lane = tid & 31;
#pragma unroll
        for (int u = 0; u < 4; u++) {
            int row = m0 + ty * 4 + u;
            float s = acc[u][0] + acc[u][1] + acc[u][2] + acc[u][3];
            float q = acc[u][0] * acc[u][0] + acc[u][1] * acc[u][1] +
                      acc[u][2] * acc[u][2] + acc[u][3] * acc[u][3];
#pragma unroll
            for (int o = 8; o > 0; o >>= 1) {
                s += __shfl_xor_sync(~0u, s, o);
                q += __shfl_xor_sync(~0u, q, o);
            }
            if ((lane & 15) == 0 && row < M) {
                atomicAdd(&g_sums[row], s);
                atomicAdd(&g_sumsq[row], q);
            }
        }
    }
}

// ---------------- zero init ----------------
__global__ __launch_bounds__(256) void zeroM_kernel() {
    for (int i = threadIdx.x + blockIdx.x * 256; i < NB * 32 * 32; i += gridDim.x * 256)
        g_M[i] = 0.f;
}
__global__ __launch_bounds__(128) void zeroStats_kernel() {
    g_sums[threadIdx.x] = 0.f;
    g_sumsq[threadIdx.x] = 0.f;
}

// ---------------- BN scale/shift from stats; re-zero stats ----------------
__global__ void scale_kernel(const float* __restrict__ gw, const float* __restrict__ bw, int Co) {
    const int o = threadIdx.x;
    if (o < Co) {
        const float invM = 1.f / (float)(NB * NN);
        float mean = g_sums[o] * invM;
        float var = g_sumsq[o] * invM - mean * mean;
        float sc = rsqrtf(var + 1e-5f) * gw[o];
        g_scale[o] = sc;
        g_shift[o] = bw[o] - mean * sc;
    }
    __syncthreads();
    g_sums[o] = 0.f;
    g_sumsq[o] = 0.f;
}

// ---------------- BN+relu+fp16 split (layer0 output -> expB input planes) ----
__global__ __launch_bounds__(256) void bnrelu_split_kernel(
    const float* __restrict__ y, __half* __restrict__ d0, __half* __restrict__ d1) {
    const int total = NB * 128 * NN;
    for (int idx = blockIdx.x * blockDim.x + threadIdx.x; idx < total;
         idx += gridDim.x * blockDim.x) {
        int o = (idx >> 12) & 127;
        float v = fmaxf(y[idx] * g_scale[o] + g_shift[o], 0.f);
        __half h0, h1;
        split2h(v, h0, h1);
        d0[idx] = h0;
        d1[idx] = h1;
    }
}

// ---------------- BN + channel softmax (layer3 output -> p) ----------------
__global__ __launch_bounds__(256) void chsoftmax_bn_kernel(const float* __restrict__ yin,
                                                           float* __restrict__ outp) {
    const int n = blockIdx.x * blockDim.x + threadIdx.x;
    const int b = blockIdx.y;
    const size_t base = (size_t)b * 32 * NN + n;
    float v[32];
    float mx = -3.4e38f;
#pragma unroll
    for (int c = 0; c < 32; c++) {
        v[c] = fmaxf(yin[base + (size_t)c * NN] * g_scale[c] + g_shift[c], 0.f);
        mx = fmaxf(mx, v[c]);
    }
    float s = 0.f;
#pragma unroll
    for (int c = 0; c < 32; c++) {
        float e = __expf(v[c] - mx);
        v[c] = e;
        s += e;
    }
    float inv = 1.f / s;
#pragma unroll
    for (int c = 0; c < 32; c++) outp[base + (size_t)c * NN] = v[c] * inv;
}

// ---------------- p p^T / finalize ----------------
__global__ __launch_bounds__(1024) void ppt_kernel(const float* __restrict__ p) {
    __shared__ float sp[32][129];
    const int b = blockIdx.y;
    const int nc = blockIdx.x * 128;
    const int tid = threadIdx.x;
    for (int t = tid; t < 32 * 128; t += 1024) {
        int c = t >> 7, n = t & 127;
        sp[c][n] = p[(size_t)b * 32 * NN + (size_t)c * NN + nc + n];
    }
    __syncthreads();
    const int i = tid >> 5, j = tid & 31;
    float acc = 0.f;
#pragma unroll 8
    for (int n = 0; n < 128; n++) acc += sp[i][n] * sp[j][n];
    atomicAdd(&g_M[b * 1024 + tid], acc);
}

__global__ __launch_bounds__(1024) void finalize_kernel(float* __restrict__ outp) {
    const int b = blockIdx.x;
    const int tid = threadIdx.x;
    float m = g_M[b * 1024 + tid];
    float d = (((tid >> 5) == (tid & 31)) ? 1.f : 0.f) - m;
    __shared__ float red[1024];
    red[tid] = d * d;
    __syncthreads();
    for (int s = 512; s > 0; s >>= 1) {
        if (tid < s) red[tid] += red[tid + s];
        __syncthreads();
    }
    if (tid == 0) outp[(size_t)NB * 32 * NN + b] = sqrtf(red[0]);
}

// ---------------- launch ----------------
extern "C" void kernel_launch(void* const* d_in, const int* in_sizes, int n_in,
                              void* d_out, int out_size) {
    const float* x = (const float*)d_in[0];
    const float *w[4], *g[4], *bb[4];
    if (n_in >= 13 && in_sizes[2] == 128 && in_sizes[3] == 128 && in_sizes[4] == 16384) {
        for (int i = 0; i < 4; i++) {
            w[i] = (const float*)d_in[1 + 3 * i];
            g[i] = (const float*)d_in[2 + 3 * i];
            bb[i] = (const float*)d_in[3 + 3 * i];
        }
    } else {
        for (int i = 0; i < 4; i++) {
            w[i] = (const float*)d_in[1 + i];
            g[i] = (const float*)d_in[5 + i];
            bb[i] = (const float*)d_in[9 + i];
        }
    }
    float* out = (float*)d_out;

    float *A, *T, *Y, *X, *MX;
    __half *XS, *XT;
    cudaGetSymbolAddress((void**)&A, g_A);
    cudaGetSymbolAddress((void**)&T, g_t);
    cudaGetSymbolAddress((void**)&Y, g_y);
    cudaGetSymbolAddress((void**)&X, g_x);
    cudaGetSymbolAddress((void**)&MX, g_mx);
    cudaGetSymbolAddress((void**)&XS, g_xs);
    cudaGetSymbolAddress((void**)&XT, g_xT);

    cudaFuncSetAttribute(mma_gemm<1>, cudaFuncAttributeMaxDynamicSharedMemorySize, 81920);
    cudaFuncSetAttribute(mma_gemm_expB, cudaFuncAttributeMaxDynamicSharedMemorySize, 102400);

    const size_t sBig = (size_t)128 * NN;
    const size_t pSmall = (size_t)NB * sBig;

    // launch order puts expB in the profiled (4th) slot this round
    xsplit_kernel<<<dim3(128, 4, NB), 256>>>(x, XS, XS + pSmall, XT, XT + pSmall);

    // S = x^T x (fp16x3 split mma, symmetric, fused partial softmax stats)
    mma_gemm<1><<<dim3(32, 32, NB), 256, 81920>>>(
        XT, pSmall, 128, (size_t)NN * 128,
        XT, pSmall, 128, (size_t)NN * 128,
        A, NN, NSQ, 128);
    rowfin_kernel<<<dim3(512, NB), 256>>>();

    // layer 0: t = x @ A (fused exp-B, split-K=2 -> T,Y) ; y = w0*(T+Y) -> X
    mma_gemm_expB<<<dim3(32, 2, NB), 256, 102400>>>(XS, pSmall, A, MX, T, Y);
    zeroStats_kernel<<<1, 128>>>();
    gemm64_kernel<1, 0, 1><<<dim3(64, 2, NB), 256>>>(w[0], 128, T, Y, sBig, X, sBig, 128, 128);
    scale_kernel<<<1, 128>>>(g[0], bb[0], 128);
    bnrelu_split_kernel<<<2048, 256>>>(X, XS, XS + pSmall);

    // layer 1: t = X @ A (fused exp-B, split-K=2 -> T,Y) ; y = w1*(T+Y) -> X
    mma_gemm_expB<<<dim3(32, 2, NB), 256, 102400>>>(XS, pSmall, A, MX, T, Y);
    gemm64_kernel<1, 0, 1><<<dim3(64, 2, NB), 256>>>(w[1], 128, T, Y, sBig, X, sBig, 128, 128);
    scale_kernel<<<1, 128>>>(g[1], bb[1], 128);

    // layer 2: y = w2 * BN(X) (128->64) -> T
    gemm64_kernel<0, 1, 1><<<dim3(64, 1, NB), 256>>>(w[2], 128, X, nullptr, sBig, T, (size_t)64 * NN, 64, 128);
    scale_kernel<<<1, 128>>>(g[2], bb[2], 64);

    // layer 3: y = w3 * BN(T) (64->32) -> Y
    gemm64_kernel<0, 1, 1><<<dim3(64, 1, NB), 256>>>(w[3], 64, T, nullptr, (size_t)64 * NN, Y, (size_t)32 * NN, 32, 64);
    scale_kernel<<<1, 128>>>(g[3], bb[3], 32);

    // p = BN + softmax over channels -> out; l = ||I - p p^T||_F per batch
    zeroM_kernel<<<16, 256>>>();
    chsoftmax_bn_kernel<<<dim3(16, NB), 256>>>(Y, out);
    ppt_kernel<<<dim3(32, NB), 1024>>>(out);
    finalize_kernel<<<NB, 1024>>>(out);
}